// round 1
// baseline (speedup 1.0000x reference)
#include <cuda_runtime.h>

// ---------------- problem dims (fixed by the dataset) ----------------
#define BB 4
#define NN 1024
#define DD 1024
#define HH 16
#define HD 64
#define ROWS (BB*NN)      // 4096
#define QKVN (3*DD)       // 3072

// ---------------- scratch (device globals; no cudaMalloc allowed) ----
__device__ float g_gamma[BB*DD];
__device__ float g_beta[BB*DD];
__device__ float g_h[ROWS*DD];        // SLN(hidden)
__device__ float g_q[BB*HH*NN*HD];
__device__ float g_k[BB*HH*NN*HD];
__device__ float g_v[BB*HH*NN*HD];
__device__ float g_ao[ROWS*DD];       // attention out, [b,n,head*64+d]
__device__ float g_h1[ROWS*DD];       // proj out + hidden

// =====================================================================
// K1: gamma[b,d] = w[b,:]·Wg[d,:] + bg[d];  beta likewise.
// one warp per output d, lanes split K (coalesced), shuffle reduce.
// =====================================================================
__global__ void __launch_bounds__(256) gammabeta_kernel(
    const float* __restrict__ w,  const float* __restrict__ Wg,
    const float* __restrict__ bg, const float* __restrict__ Wb,
    const float* __restrict__ bb)
{
    int lane = threadIdx.x & 31;
    int warp = threadIdx.x >> 5;
    int gid  = blockIdx.x * 8 + warp;       // 0..4095
    int b = gid >> 10, d = gid & 1023;
    const float* wrow = w  + b * DD;
    const float* wg   = Wg + (size_t)d * DD;
    const float* wb   = Wb + (size_t)d * DD;
    float sg = 0.f, sb = 0.f;
    #pragma unroll 4
    for (int k = lane; k < DD; k += 32) {
        float wk = wrow[k];
        sg = fmaf(wk, wg[k], sg);
        sb = fmaf(wk, wb[k], sb);
    }
    #pragma unroll
    for (int o = 16; o; o >>= 1) {
        sg += __shfl_xor_sync(0xffffffffu, sg, o);
        sb += __shfl_xor_sync(0xffffffffu, sb, o);
    }
    if (!lane) {
        g_gamma[gid] = sg + bg[d];
        g_beta[gid]  = sb + bb[d];
    }
}

// =====================================================================
// SLN: layernorm (biased var) * ln_g + ln_b, then gamma*ln + beta.
// one block per row, 256 threads, 4 elems/thread via float4.
// =====================================================================
__device__ __forceinline__ void row_stats(float4 xv, float& mu, float& rstd,
                                          float* red)
{
    float s = xv.x + xv.y + xv.z + xv.w;
    float q = xv.x*xv.x + xv.y*xv.y + xv.z*xv.z + xv.w*xv.w;
    #pragma unroll
    for (int o = 16; o; o >>= 1) {
        s += __shfl_xor_sync(0xffffffffu, s, o);
        q += __shfl_xor_sync(0xffffffffu, q, o);
    }
    int warp = threadIdx.x >> 5, lane = threadIdx.x & 31;
    if (!lane) { red[warp] = s; red[8 + warp] = q; }
    __syncthreads();
    float ss = 0.f, qq = 0.f;
    #pragma unroll
    for (int i = 0; i < 8; i++) { ss += red[i]; qq += red[8 + i]; }
    mu = ss * (1.0f / DD);
    float var = qq * (1.0f / DD) - mu * mu;
    rstd = rsqrtf(var + 1e-5f);
}

__global__ void __launch_bounds__(256) sln1_kernel(
    const float* __restrict__ x, const float* __restrict__ ln_g,
    const float* __restrict__ ln_b)
{
    __shared__ float red[16];
    int row = blockIdx.x;
    int b = row >> 10;
    float4 xv = *(const float4*)(x + (size_t)row * DD + threadIdx.x * 4);
    float mu, rstd;
    row_stats(xv, mu, rstd, red);
    int d = threadIdx.x * 4;
    float4 g  = *(const float4*)(ln_g + d);
    float4 lb = *(const float4*)(ln_b + d);
    float4 ga = *(const float4*)(g_gamma + b * DD + d);
    float4 be = *(const float4*)(g_beta  + b * DD + d);
    float4 y;
    y.x = fmaf(ga.x, fmaf((xv.x - mu) * rstd, g.x, lb.x), be.x);
    y.y = fmaf(ga.y, fmaf((xv.y - mu) * rstd, g.y, lb.y), be.y);
    y.z = fmaf(ga.z, fmaf((xv.z - mu) * rstd, g.z, lb.z), be.z);
    y.w = fmaf(ga.w, fmaf((xv.w - mu) * rstd, g.w, lb.w), be.w);
    *(float4*)&g_h[(size_t)row * DD + d] = y;
}

// final: out = SLN(h1)*gamma+beta + h1
__global__ void __launch_bounds__(256) sln2_kernel(
    const float* __restrict__ ln_g, const float* __restrict__ ln_b,
    float* __restrict__ out)
{
    __shared__ float red[16];
    int row = blockIdx.x;
    int b = row >> 10;
    float4 xv = *(const float4*)(g_h1 + (size_t)row * DD + threadIdx.x * 4);
    float mu, rstd;
    row_stats(xv, mu, rstd, red);
    int d = threadIdx.x * 4;
    float4 g  = *(const float4*)(ln_g + d);
    float4 lb = *(const float4*)(ln_b + d);
    float4 ga = *(const float4*)(g_gamma + b * DD + d);
    float4 be = *(const float4*)(g_beta  + b * DD + d);
    float4 y;
    y.x = fmaf(ga.x, fmaf((xv.x - mu) * rstd, g.x, lb.x), be.x) + xv.x;
    y.y = fmaf(ga.y, fmaf((xv.y - mu) * rstd, g.y, lb.y), be.y) + xv.y;
    y.z = fmaf(ga.z, fmaf((xv.z - mu) * rstd, g.z, lb.z), be.z) + xv.z;
    y.w = fmaf(ga.w, fmaf((xv.w - mu) * rstd, g.w, lb.w), be.w) + xv.w;
    *(float4*)&out[(size_t)row * DD + d] = y;
}

// =====================================================================
// Tiled fp32 GEMM, 128x128x16, 256 threads, 8x8 regs per thread.
// =====================================================================
#define GBM 128
#define GBN 128
#define GBK 16
#define GPAD 132

// QKV: C[row, j] = g_h[row,:]·Wqkv[perm(j),:] + bqkv[perm(j)],
// scattered so q/k/v land contiguous [B,H,N,hd].
__global__ void __launch_bounds__(256, 2) qkv_gemm_kernel(
    const float* __restrict__ Wqkv, const float* __restrict__ bqkv)
{
    __shared__ float As[GBK][GPAD];
    __shared__ float Bs[GBK][GPAD];
    const int tid = threadIdx.x;
    const int tx = tid & 15, ty = tid >> 4;
    const int bm = blockIdx.y * GBM;
    const int bn = blockIdx.x * GBN;
    const int lr = tid >> 2;             // 0..63
    const int lc = (tid & 3) << 2;       // 0,4,8,12

    const float* A0 = g_h + (size_t)(bm + lr) * DD;
    const float* A1 = g_h + (size_t)(bm + lr + 64) * DD;
    int j0 = bn + lr, j1 = bn + lr + 64;
    int p0 = ((j0 & 1023) >> 6) * 192 + (j0 & 63) * 3 + (j0 >> 10);
    int p1 = ((j1 & 1023) >> 6) * 192 + (j1 & 63) * 3 + (j1 >> 10);
    const float* B0 = Wqkv + (size_t)p0 * DD;
    const float* B1 = Wqkv + (size_t)p1 * DD;

    float acc[8][8];
    #pragma unroll
    for (int i = 0; i < 8; i++)
        #pragma unroll
        for (int j = 0; j < 8; j++) acc[i][j] = 0.f;

    for (int k0 = 0; k0 < DD; k0 += GBK) {
        float4 a0 = *(const float4*)(A0 + k0 + lc);
        float4 a1 = *(const float4*)(A1 + k0 + lc);
        float4 b0 = *(const float4*)(B0 + k0 + lc);
        float4 b1 = *(const float4*)(B1 + k0 + lc);
        __syncthreads();
        As[lc+0][lr] = a0.x; As[lc+1][lr] = a0.y; As[lc+2][lr] = a0.z; As[lc+3][lr] = a0.w;
        As[lc+0][lr+64] = a1.x; As[lc+1][lr+64] = a1.y; As[lc+2][lr+64] = a1.z; As[lc+3][lr+64] = a1.w;
        Bs[lc+0][lr] = b0.x; Bs[lc+1][lr] = b0.y; Bs[lc+2][lr] = b0.z; Bs[lc+3][lr] = b0.w;
        Bs[lc+0][lr+64] = b1.x; Bs[lc+1][lr+64] = b1.y; Bs[lc+2][lr+64] = b1.z; Bs[lc+3][lr+64] = b1.w;
        __syncthreads();
        #pragma unroll
        for (int k = 0; k < GBK; k++) {
            float ar[8], br[8];
            *(float4*)(ar)     = *(const float4*)&As[k][ty*4];
            *(float4*)(ar + 4) = *(const float4*)&As[k][ty*4 + 64];
            *(float4*)(br)     = *(const float4*)&Bs[k][tx*4];
            *(float4*)(br + 4) = *(const float4*)&Bs[k][tx*4 + 64];
            #pragma unroll
            for (int i = 0; i < 8; i++)
                #pragma unroll
                for (int j = 0; j < 8; j++)
                    acc[i][j] = fmaf(ar[i], br[j], acc[i][j]);
        }
    }

    // epilogue: add bias, scatter into q/k/v [B,H,N,hd]
    #pragma unroll
    for (int jg = 0; jg < 2; jg++) {
        int c0 = bn + tx * 4 + jg * 64;         // 4 consecutive logical cols
        int arr = c0 >> 10, rem = c0 & 1023;
        int head = rem >> 6, dd = rem & 63;
        float* dst = (arr == 0) ? g_q : (arr == 1) ? g_k : g_v;
        float4 bias;
        bias.x = bqkv[head*192 + (dd+0)*3 + arr];
        bias.y = bqkv[head*192 + (dd+1)*3 + arr];
        bias.z = bqkv[head*192 + (dd+2)*3 + arr];
        bias.w = bqkv[head*192 + (dd+3)*3 + arr];
        #pragma unroll
        for (int ig = 0; ig < 2; ig++)
            #pragma unroll
            for (int i = 0; i < 4; i++) {
                int grow = bm + ig * 64 + ty * 4 + i;
                int b = grow >> 10, n = grow & 1023;
                float4 o;
                o.x = acc[ig*4+i][jg*4+0] + bias.x;
                o.y = acc[ig*4+i][jg*4+1] + bias.y;
                o.z = acc[ig*4+i][jg*4+2] + bias.z;
                o.w = acc[ig*4+i][jg*4+3] + bias.w;
                *(float4*)&dst[(((size_t)(b*HH + head))*NN + n)*HD + dd] = o;
            }
    }
}

// Proj: g_h1 = g_ao @ Wp^T + bp + hidden
__global__ void __launch_bounds__(256, 2) proj_gemm_kernel(
    const float* __restrict__ Wp, const float* __restrict__ bp,
    const float* __restrict__ hidden)
{
    __shared__ float As[GBK][GPAD];
    __shared__ float Bs[GBK][GPAD];
    const int tid = threadIdx.x;
    const int tx = tid & 15, ty = tid >> 4;
    const int bm = blockIdx.y * GBM;
    const int bn = blockIdx.x * GBN;
    const int lr = tid >> 2;
    const int lc = (tid & 3) << 2;

    const float* A0 = g_ao + (size_t)(bm + lr) * DD;
    const float* A1 = g_ao + (size_t)(bm + lr + 64) * DD;
    const float* B0 = Wp + (size_t)(bn + lr) * DD;
    const float* B1 = Wp + (size_t)(bn + lr + 64) * DD;

    float acc[8][8];
    #pragma unroll
    for (int i = 0; i < 8; i++)
        #pragma unroll
        for (int j = 0; j < 8; j++) acc[i][j] = 0.f;

    for (int k0 = 0; k0 < DD; k0 += GBK) {
        float4 a0 = *(const float4*)(A0 + k0 + lc);
        float4 a1 = *(const float4*)(A1 + k0 + lc);
        float4 b0 = *(const float4*)(B0 + k0 + lc);
        float4 b1 = *(const float4*)(B1 + k0 + lc);
        __syncthreads();
        As[lc+0][lr] = a0.x; As[lc+1][lr] = a0.y; As[lc+2][lr] = a0.z; As[lc+3][lr] = a0.w;
        As[lc+0][lr+64] = a1.x; As[lc+1][lr+64] = a1.y; As[lc+2][lr+64] = a1.z; As[lc+3][lr+64] = a1.w;
        Bs[lc+0][lr] = b0.x; Bs[lc+1][lr] = b0.y; Bs[lc+2][lr] = b0.z; Bs[lc+3][lr] = b0.w;
        Bs[lc+0][lr+64] = b1.x; Bs[lc+1][lr+64] = b1.y; Bs[lc+2][lr+64] = b1.z; Bs[lc+3][lr+64] = b1.w;
        __syncthreads();
        #pragma unroll
        for (int k = 0; k < GBK; k++) {
            float ar[8], br[8];
            *(float4*)(ar)     = *(const float4*)&As[k][ty*4];
            *(float4*)(ar + 4) = *(const float4*)&As[k][ty*4 + 64];
            *(float4*)(br)     = *(const float4*)&Bs[k][tx*4];
            *(float4*)(br + 4) = *(const float4*)&Bs[k][tx*4 + 64];
            #pragma unroll
            for (int i = 0; i < 8; i++)
                #pragma unroll
                for (int j = 0; j < 8; j++)
                    acc[i][j] = fmaf(ar[i], br[j], acc[i][j]);
        }
    }

    #pragma unroll
    for (int jg = 0; jg < 2; jg++) {
        int col = bn + tx * 4 + jg * 64;
        float4 bias = *(const float4*)(bp + col);
        #pragma unroll
        for (int ig = 0; ig < 2; ig++)
            #pragma unroll
            for (int i = 0; i < 4; i++) {
                int grow = bm + ig * 64 + ty * 4 + i;
                float4 hres = *(const float4*)(hidden + (size_t)grow * DD + col);
                float4 o;
                o.x = acc[ig*4+i][jg*4+0] + bias.x + hres.x;
                o.y = acc[ig*4+i][jg*4+1] + bias.y + hres.y;
                o.z = acc[ig*4+i][jg*4+2] + bias.z + hres.z;
                o.w = acc[ig*4+i][jg*4+3] + bias.w + hres.w;
                *(float4*)&g_h1[(size_t)grow * DD + col] = o;
            }
    }
}

// =====================================================================
// Flash attention: 64-query tiles, hd=64, online softmax.
// NOTE the source quirk: softmax first, THEN divide by sqrt(D)=32.
// No pre-softmax scaling of logits. Final: o/(l*32).
// =====================================================================
#define AW 68
#define ATTN_SMEM (4 * 64 * AW * 4)

__global__ void __launch_bounds__(256, 2) attn_kernel()
{
    extern __shared__ float sm[];
    float* Qt = sm;                 // [kk][qi]
    float* Kt = sm + 64 * AW;       // [kk][kj]
    float* Vs = sm + 2 * 64 * AW;   // [kj][d]
    float* Ps = sm + 3 * 64 * AW;   // [kj][qi]

    const int tid = threadIdx.x;
    const int tx = tid & 15, ty = tid >> 4;
    const int lr = tid >> 2;
    const int lcb = (tid & 3) << 2;
    const int bh = blockIdx.y;      // b*16 + head
    const int qt = blockIdx.x;

    const float* Qg = g_q + ((size_t)bh * NN + qt * 64) * HD;
    const float* Kg = g_k + (size_t)bh * NN * HD;
    const float* Vg = g_v + (size_t)bh * NN * HD;

    #pragma unroll
    for (int p = 0; p < 4; p++) {
        int c = lcb + (p << 4);
        float4 qv = *(const float4*)(Qg + lr * HD + c);
        Qt[(c+0)*AW + lr] = qv.x;
        Qt[(c+1)*AW + lr] = qv.y;
        Qt[(c+2)*AW + lr] = qv.z;
        Qt[(c+3)*AW + lr] = qv.w;
    }

    float m[4], l[4], o[4][4];
    #pragma unroll
    for (int i = 0; i < 4; i++) {
        m[i] = -1e30f; l[i] = 0.f;
        #pragma unroll
        for (int j = 0; j < 4; j++) o[i][j] = 0.f;
    }

    for (int t = 0; t < 16; t++) {
        float4 kv[4], vv[4];
        #pragma unroll
        for (int p = 0; p < 4; p++) {
            int c = lcb + (p << 4);
            kv[p] = *(const float4*)(Kg + (size_t)(t*64 + lr) * HD + c);
            vv[p] = *(const float4*)(Vg + (size_t)(t*64 + lr) * HD + c);
        }
        __syncthreads();     // prior iter done reading Kt/Vs/Ps (also orders Qt at t=0)
        #pragma unroll
        for (int p = 0; p < 4; p++) {
            int c = lcb + (p << 4);
            Kt[(c+0)*AW + lr] = kv[p].x;
            Kt[(c+1)*AW + lr] = kv[p].y;
            Kt[(c+2)*AW + lr] = kv[p].z;
            Kt[(c+3)*AW + lr] = kv[p].w;
            *(float4*)&Vs[lr * AW + c] = vv[p];
        }
        __syncthreads();

        // S = Q @ K^T  (4x4 fragment per thread)
        float s[4][4];
        #pragma unroll
        for (int i = 0; i < 4; i++)
            #pragma unroll
            for (int j = 0; j < 4; j++) s[i][j] = 0.f;
        #pragma unroll 8
        for (int kk = 0; kk < 64; kk++) {
            float4 qa = *(const float4*)&Qt[kk*AW + ty*4];
            float4 kb = *(const float4*)&Kt[kk*AW + tx*4];
            float qr[4] = {qa.x, qa.y, qa.z, qa.w};
            float kr[4] = {kb.x, kb.y, kb.z, kb.w};
            #pragma unroll
            for (int i = 0; i < 4; i++)
                #pragma unroll
                for (int j = 0; j < 4; j++)
                    s[i][j] = fmaf(qr[i], kr[j], s[i][j]);
        }

        // online softmax (row stats shuffled across the 16-lane tx group)
        #pragma unroll
        for (int i = 0; i < 4; i++) {
            float rm = fmaxf(fmaxf(s[i][0], s[i][1]), fmaxf(s[i][2], s[i][3]));
            #pragma unroll
            for (int off = 8; off > 0; off >>= 1)
                rm = fmaxf(rm, __shfl_xor_sync(0xffffffffu, rm, off));
            float mn = fmaxf(m[i], rm);
            float sc = __expf(m[i] - mn);
            m[i] = mn;
            float rs = 0.f;
            #pragma unroll
            for (int j = 0; j < 4; j++) {
                s[i][j] = __expf(s[i][j] - mn);
                rs += s[i][j];
            }
            #pragma unroll
            for (int off = 8; off > 0; off >>= 1)
                rs += __shfl_xor_sync(0xffffffffu, rs, off);
            l[i] = l[i] * sc + rs;
            #pragma unroll
            for (int j = 0; j < 4; j++) o[i][j] *= sc;
        }

        // stage P transposed: Ps[kj][qi]
        #pragma unroll
        for (int j = 0; j < 4; j++)
            #pragma unroll
            for (int i = 0; i < 4; i++)
                Ps[(tx*4 + j) * AW + ty*4 + i] = s[i][j];
        __syncthreads();

        // O += P @ V
        #pragma unroll 8
        for (int kj = 0; kj < 64; kj++) {
            float4 pa = *(const float4*)&Ps[kj*AW + ty*4];
            float4 vb = *(const float4*)&Vs[kj*AW + tx*4];
            float pr[4] = {pa.x, pa.y, pa.z, pa.w};
            float vr[4] = {vb.x, vb.y, vb.z, vb.w};
            #pragma unroll
            for (int i = 0; i < 4; i++)
                #pragma unroll
                for (int j = 0; j < 4; j++)
                    o[i][j] = fmaf(pr[i], vr[j], o[i][j]);
        }
    }

    const int b = bh >> 4, head = bh & 15;
    #pragma unroll
    for (int i = 0; i < 4; i++) {
        float inv = 1.0f / (l[i] * 32.0f);   // /l then /sqrt(D)
        int n = qt * 64 + ty * 4 + i;
        float4 ov = make_float4(o[i][0]*inv, o[i][1]*inv, o[i][2]*inv, o[i][3]*inv);
        *(float4*)&g_ao[((size_t)(b * NN + n)) * DD + head * 64 + tx * 4] = ov;
    }
}

// =====================================================================
extern "C" void kernel_launch(void* const* d_in, const int* in_sizes, int n_in,
                              void* d_out, int out_size)
{
    (void)in_sizes; (void)n_in; (void)out_size;
    const float* hidden = (const float*)d_in[0];
    const float* w      = (const float*)d_in[1];
    const float* ln_g   = (const float*)d_in[2];
    const float* ln_b   = (const float*)d_in[3];
    const float* Wg     = (const float*)d_in[4];
    const float* bg     = (const float*)d_in[5];
    const float* Wb     = (const float*)d_in[6];
    const float* bb     = (const float*)d_in[7];
    const float* Wqkv   = (const float*)d_in[8];
    const float* bqkv   = (const float*)d_in[9];
    const float* Wp     = (const float*)d_in[10];
    const float* bp     = (const float*)d_in[11];
    // d_in[12..15] = W1,b1,W2,b2 : dead in the reference (output discarded)
    float* out = (float*)d_out;

    gammabeta_kernel<<<512, 256>>>(w, Wg, bg, Wb, bb);
    sln1_kernel<<<ROWS, 256>>>(hidden, ln_g, ln_b);
    qkv_gemm_kernel<<<dim3(QKVN / GBN, ROWS / GBM), 256>>>(Wqkv, bqkv);
    cudaFuncSetAttribute(attn_kernel, cudaFuncAttributeMaxDynamicSharedMemorySize, ATTN_SMEM);
    attn_kernel<<<dim3(NN / 64, BB * HH), 256, ATTN_SMEM>>>();
    proj_gemm_kernel<<<dim3(DD / GBN, ROWS / GBM), 256>>>(Wp, bp, hidden);
    sln2_kernel<<<ROWS, 256>>>(ln_g, ln_b, out);
}

// round 3
// speedup vs baseline: 1.6067x; 1.6067x over previous
#include <cuda_runtime.h>
#include <cstdint>

// ---------------- problem dims ----------------
#define BB 4
#define NN 1024
#define DD 1024
#define HH 16
#define HD 64
#define ROWS (BB*NN)      // 4096
#define QKVN (3*DD)       // 3072

// ---------------- scratch ----------------
__device__ float g_gamma[BB*DD];
__device__ float g_beta[BB*DD];
__device__ float g_h[ROWS*DD];
__device__ float g_q[BB*HH*NN*HD];
__device__ float g_k[BB*HH*NN*HD];
__device__ float g_v[BB*HH*NN*HD];
__device__ float g_ao[ROWS*DD];
__device__ float g_h1[ROWS*DD];

// ================= mma.sync tf32 helpers =================
__device__ __forceinline__ uint32_t f2tf32(float f) {
    uint32_t r; asm("cvt.rna.tf32.f32 %0, %1;" : "=r"(r) : "f"(f)); return r;
}
__device__ __forceinline__ float tff(float f) {       // tf32 bits stored as float
    return __uint_as_float(f2tf32(f));
}
__device__ __forceinline__ void mma_tf32(float* d, const uint32_t* a,
                                         uint32_t b0, uint32_t b1) {
    asm volatile("mma.sync.aligned.m16n8k8.row.col.f32.tf32.tf32.f32 "
        "{%0,%1,%2,%3}, {%4,%5,%6,%7}, {%8,%9}, {%0,%1,%2,%3};"
        : "+f"(d[0]), "+f"(d[1]), "+f"(d[2]), "+f"(d[3])
        : "r"(a[0]), "r"(a[1]), "r"(a[2]), "r"(a[3]), "r"(b0), "r"(b1));
}

// =====================================================================
// GEMM via mma.sync tf32: C[128x128] per block, K=1024 in 64 stages of 16.
// smem rows hold 16 k-values permuted so (c, c+4) pairs are adjacent:
//   pos(k) = (k>>3)*8 + 2*(k&3) + ((k>>2)&1)
// =====================================================================
#define MMSTRIDE 20   // 16 + 4 pad (floats)

template<int QKV>
__global__ void __launch_bounds__(256) mm_mma(
    const float* __restrict__ Bw, const float* __restrict__ bias,
    const float* __restrict__ resid)
{
    __shared__ float As[2][128 * MMSTRIDE];
    __shared__ float Bs[2][128 * MMSTRIDE];

    const int tid  = threadIdx.x;
    const int lane = tid & 31, wid = tid >> 5;
    const int bm = blockIdx.y * 128, bn = blockIdx.x * 128;
    const float* Asrc = QKV ? g_h : g_ao;

    // ---- loader mapping: thread -> (row r, col-half hh) ----
    const int r  = tid >> 1;
    const int hh = tid & 1;
    const float* aptr = Asrc + (size_t)(bm + r) * DD + hh * 8;
    int j = bn + r;
    int bj = QKV ? (((j & 1023) >> 6) * 192 + (j & 63) * 3 + (j >> 10)) : j;
    const float* bptr = Bw + (size_t)bj * DD + hh * 8;
    const int soff = r * MMSTRIDE + hh * 8;

    // ---- warp tile mapping ----
    const int wm = (wid & 1) * 64;
    const int wn = (wid >> 1) * 32;
    const int g  = lane >> 2;            // group id (rows / n within 8)
    const int cc = lane & 3;
    const int c2 = cc * 2;

    float acc[4][4][4];
    #pragma unroll
    for (int mt = 0; mt < 4; mt++)
        #pragma unroll
        for (int nt = 0; nt < 4; nt++)
            #pragma unroll
            for (int e = 0; e < 4; e++) acc[mt][nt][e] = 0.f;

    // prefetch regs
    float4 ra0, ra1, rb0, rb1;
    ra0 = *(const float4*)(aptr);     ra1 = *(const float4*)(aptr + 4);
    rb0 = *(const float4*)(bptr);     rb1 = *(const float4*)(bptr + 4);

    // store stage 0
    {
        float2* da = (float2*)&As[0][soff];
        da[0] = make_float2(tff(ra0.x), tff(ra1.x));
        da[1] = make_float2(tff(ra0.y), tff(ra1.y));
        da[2] = make_float2(tff(ra0.z), tff(ra1.z));
        da[3] = make_float2(tff(ra0.w), tff(ra1.w));
        float2* db = (float2*)&Bs[0][soff];
        db[0] = make_float2(tff(rb0.x), tff(rb1.x));
        db[1] = make_float2(tff(rb0.y), tff(rb1.y));
        db[2] = make_float2(tff(rb0.z), tff(rb1.z));
        db[3] = make_float2(tff(rb0.w), tff(rb1.w));
    }
    __syncthreads();

    for (int t = 0; t < 64; t++) {
        const int buf = t & 1;
        if (t < 63) {
            const float* ap = aptr + (t + 1) * 16;
            const float* bp = bptr + (t + 1) * 16;
            ra0 = *(const float4*)(ap);     ra1 = *(const float4*)(ap + 4);
            rb0 = *(const float4*)(bp);     rb1 = *(const float4*)(bp + 4);
        }
        #pragma unroll
        for (int kc = 0; kc < 2; kc++) {
            uint32_t af[4][4], bf[4][2];
            #pragma unroll
            for (int mt = 0; mt < 4; mt++) {
                const float* pa = &As[buf][(wm + mt * 16 + g) * MMSTRIDE + kc * 8 + c2];
                float2 lo = *(const float2*)pa;
                float2 hi = *(const float2*)(pa + 8 * MMSTRIDE);
                af[mt][0] = __float_as_uint(lo.x);
                af[mt][1] = __float_as_uint(hi.x);
                af[mt][2] = __float_as_uint(lo.y);
                af[mt][3] = __float_as_uint(hi.y);
            }
            #pragma unroll
            for (int nt = 0; nt < 4; nt++) {
                float2 bb = *(const float2*)&Bs[buf][(wn + nt * 8 + g) * MMSTRIDE + kc * 8 + c2];
                bf[nt][0] = __float_as_uint(bb.x);
                bf[nt][1] = __float_as_uint(bb.y);
            }
            #pragma unroll
            for (int mt = 0; mt < 4; mt++)
                #pragma unroll
                for (int nt = 0; nt < 4; nt++)
                    mma_tf32(acc[mt][nt], af[mt], bf[nt][0], bf[nt][1]);
        }
        if (t < 63) {
            float2* da = (float2*)&As[buf ^ 1][soff];
            da[0] = make_float2(tff(ra0.x), tff(ra1.x));
            da[1] = make_float2(tff(ra0.y), tff(ra1.y));
            da[2] = make_float2(tff(ra0.z), tff(ra1.z));
            da[3] = make_float2(tff(ra0.w), tff(ra1.w));
            float2* db = (float2*)&Bs[buf ^ 1][soff];
            db[0] = make_float2(tff(rb0.x), tff(rb1.x));
            db[1] = make_float2(tff(rb0.y), tff(rb1.y));
            db[2] = make_float2(tff(rb0.z), tff(rb1.z));
            db[3] = make_float2(tff(rb0.w), tff(rb1.w));
        }
        __syncthreads();
    }

    // ---- epilogue ----
    #pragma unroll
    for (int mt = 0; mt < 4; mt++) {
        #pragma unroll
        for (int nt = 0; nt < 4; nt++) {
            int R0 = bm + wm + mt * 16 + g;
            int C  = bn + wn + nt * 8 + c2;
            float v00 = acc[mt][nt][0], v01 = acc[mt][nt][1];
            float v10 = acc[mt][nt][2], v11 = acc[mt][nt][3];
            if (QKV) {
                int arr = C >> 10, rem = C & 1023;
                int head = rem >> 6, dd = rem & 63;
                float bx = bias[head * 192 + dd * 3 + arr];
                float by = bias[head * 192 + (dd + 1) * 3 + arr];
                float* dst = (arr == 0) ? g_q : (arr == 1) ? g_k : g_v;
                int b0 = R0 >> 10, n0 = R0 & 1023;
                size_t base = (((size_t)(b0 * HH + head)) * NN);
                *(float2*)&dst[(base + n0) * HD + dd] =
                    make_float2(v00 + bx, v01 + by);
                *(float2*)&dst[(base + n0 + 8) * HD + dd] =
                    make_float2(v10 + bx, v11 + by);
            } else {
                float2 bb = *(const float2*)(bias + C);
                float2 h0 = *(const float2*)(resid + (size_t)R0 * DD + C);
                float2 h1 = *(const float2*)(resid + (size_t)(R0 + 8) * DD + C);
                *(float2*)&g_h1[(size_t)R0 * DD + C] =
                    make_float2(v00 + bb.x + h0.x, v01 + bb.y + h0.y);
                *(float2*)&g_h1[(size_t)(R0 + 8) * DD + C] =
                    make_float2(v10 + bb.x + h1.x, v11 + bb.y + h1.y);
            }
        }
    }
}

// =====================================================================
// Flash attention via mma.sync tf32.
// Block: 256 threads = 8 warps; 128 queries (16 per warp). 16 key tiles of 64.
// Ks[key][pos(dim)]  (pairs (k,k+4) adjacent)   stride 68
// Vs[dim][pos(key)]  (pairs (k,k+4) adjacent)   stride 68
// Ps[warp][16][68]   P staging for A-fragment reload
// =====================================================================
#define ATS 68
#define ATTN_SMEM_B ((2 * 64 * ATS + 8 * 16 * ATS) * 4)   // 69632 bytes

__device__ __forceinline__ int sperm64(int x) {
    return (x & ~7) + 2 * (x & 3) + ((x >> 2) & 1);
}

__global__ void __launch_bounds__(256) attn_mma()
{
    extern __shared__ float sf[];
    float* Ks = sf;
    float* Vs = sf + 64 * ATS;

    const int tid = threadIdx.x, lane = tid & 31, w = tid >> 5;
    float* Ps = sf + 2 * 64 * ATS + w * 16 * ATS;
    const int bh = blockIdx.y, qt = blockIdx.x;
    const int g = lane >> 2, cc = lane & 3, c2 = cc * 2;

    const float* Qg = g_q + ((size_t)bh * NN + qt * 128 + w * 16) * HD;
    const float* Kg = g_k + (size_t)bh * NN * HD;
    const float* Vg = g_v + (size_t)bh * NN * HD;

    // Q fragments, resident for the whole kernel
    uint32_t qf[8][4];
    #pragma unroll
    for (int kc = 0; kc < 8; kc++) {
        qf[kc][0] = f2tf32(Qg[g * HD + kc * 8 + cc]);
        qf[kc][1] = f2tf32(Qg[(g + 8) * HD + kc * 8 + cc]);
        qf[kc][2] = f2tf32(Qg[g * HD + kc * 8 + cc + 4]);
        qf[kc][3] = f2tf32(Qg[(g + 8) * HD + kc * 8 + cc + 4]);
    }

    // fill mapping: thread -> key (0..63), dim group (16 dims)
    const int fkey = tid & 63;
    const int fd0  = (tid >> 6) * 16;
    const int spk  = sperm64(fkey);

    float o[8][4];
    #pragma unroll
    for (int nt = 0; nt < 8; nt++)
        #pragma unroll
        for (int e = 0; e < 4; e++) o[nt][e] = 0.f;
    float m0 = -1e30f, m1 = -1e30f, l0 = 0.f, l1 = 0.f;

    float4 kr[4], vr[4];
    #pragma unroll
    for (int i = 0; i < 4; i++) {
        kr[i] = *(const float4*)(Kg + (size_t)fkey * HD + fd0 + i * 4);
        vr[i] = *(const float4*)(Vg + (size_t)fkey * HD + fd0 + i * 4);
    }
    // store tile 0
    #pragma unroll
    for (int i = 0; i < 4; i++) {
        int d = fd0 + i * 4;
        float* kdst = &Ks[fkey * ATS];
        kdst[sperm64(d + 0)] = tff(kr[i].x);
        kdst[sperm64(d + 1)] = tff(kr[i].y);
        kdst[sperm64(d + 2)] = tff(kr[i].z);
        kdst[sperm64(d + 3)] = tff(kr[i].w);
        Vs[(d + 0) * ATS + spk] = tff(vr[i].x);
        Vs[(d + 1) * ATS + spk] = tff(vr[i].y);
        Vs[(d + 2) * ATS + spk] = tff(vr[i].z);
        Vs[(d + 3) * ATS + spk] = tff(vr[i].w);
    }
    __syncthreads();

    for (int t = 0; t < 16; t++) {
        if (t < 15) {
            const float* kp = Kg + (size_t)(t + 1) * 64 * HD + (size_t)fkey * HD + fd0;
            const float* vp = Vg + (size_t)(t + 1) * 64 * HD + (size_t)fkey * HD + fd0;
            #pragma unroll
            for (int i = 0; i < 4; i++) {
                kr[i] = *(const float4*)(kp + i * 4);
                vr[i] = *(const float4*)(vp + i * 4);
            }
        }

        // ---- S = Q K^T ----
        float s[8][4];
        #pragma unroll
        for (int nt = 0; nt < 8; nt++) {
            s[nt][0] = s[nt][1] = s[nt][2] = s[nt][3] = 0.f;
            #pragma unroll
            for (int kc = 0; kc < 8; kc++) {
                float2 bb = *(const float2*)&Ks[(nt * 8 + g) * ATS + kc * 8 + c2];
                mma_tf32(s[nt], qf[kc], __float_as_uint(bb.x), __float_as_uint(bb.y));
            }
        }

        // ---- online softmax (rows g and g+8) ----
        float rmax0 = -1e30f, rmax1 = -1e30f;
        #pragma unroll
        for (int nt = 0; nt < 8; nt++) {
            rmax0 = fmaxf(rmax0, fmaxf(s[nt][0], s[nt][1]));
            rmax1 = fmaxf(rmax1, fmaxf(s[nt][2], s[nt][3]));
        }
        rmax0 = fmaxf(rmax0, __shfl_xor_sync(0xffffffffu, rmax0, 1));
        rmax0 = fmaxf(rmax0, __shfl_xor_sync(0xffffffffu, rmax0, 2));
        rmax1 = fmaxf(rmax1, __shfl_xor_sync(0xffffffffu, rmax1, 1));
        rmax1 = fmaxf(rmax1, __shfl_xor_sync(0xffffffffu, rmax1, 2));
        float mn0 = fmaxf(m0, rmax0), mn1 = fmaxf(m1, rmax1);
        float sc0 = __expf(m0 - mn0), sc1 = __expf(m1 - mn1);
        m0 = mn0; m1 = mn1;
        float rs0 = 0.f, rs1 = 0.f;
        #pragma unroll
        for (int nt = 0; nt < 8; nt++) {
            s[nt][0] = __expf(s[nt][0] - mn0); rs0 += s[nt][0];
            s[nt][1] = __expf(s[nt][1] - mn0); rs0 += s[nt][1];
            s[nt][2] = __expf(s[nt][2] - mn1); rs1 += s[nt][2];
            s[nt][3] = __expf(s[nt][3] - mn1); rs1 += s[nt][3];
        }
        rs0 += __shfl_xor_sync(0xffffffffu, rs0, 1);
        rs0 += __shfl_xor_sync(0xffffffffu, rs0, 2);
        rs1 += __shfl_xor_sync(0xffffffffu, rs1, 1);
        rs1 += __shfl_xor_sync(0xffffffffu, rs1, 2);
        l0 = l0 * sc0 + rs0;
        l1 = l1 * sc1 + rs1;
        #pragma unroll
        for (int nt = 0; nt < 8; nt++) {
            o[nt][0] *= sc0; o[nt][1] *= sc0;
            o[nt][2] *= sc1; o[nt][3] *= sc1;
        }

        // ---- stage P (as tf32 bits) and re-fragment ----
        #pragma unroll
        for (int nt = 0; nt < 8; nt++) {
            *(float2*)&Ps[g * ATS + nt * 8 + c2] =
                make_float2(tff(s[nt][0]), tff(s[nt][1]));
            *(float2*)&Ps[(g + 8) * ATS + nt * 8 + c2] =
                make_float2(tff(s[nt][2]), tff(s[nt][3]));
        }
        __syncwarp();

        // ---- O += P V ----
        #pragma unroll
        for (int kc = 0; kc < 8; kc++) {
            uint32_t pa[4];
            pa[0] = __float_as_uint(Ps[g * ATS + kc * 8 + cc]);
            pa[1] = __float_as_uint(Ps[(g + 8) * ATS + kc * 8 + cc]);
            pa[2] = __float_as_uint(Ps[g * ATS + kc * 8 + cc + 4]);
            pa[3] = __float_as_uint(Ps[(g + 8) * ATS + kc * 8 + cc + 4]);
            #pragma unroll
            for (int nt = 0; nt < 8; nt++) {
                float2 bb = *(const float2*)&Vs[(nt * 8 + g) * ATS + kc * 8 + c2];
                mma_tf32(o[nt], pa, __float_as_uint(bb.x), __float_as_uint(bb.y));
            }
        }

        __syncthreads();          // everyone done reading Ks/Vs
        if (t < 15) {
            #pragma unroll
            for (int i = 0; i < 4; i++) {
                int d = fd0 + i * 4;
                float* kdst = &Ks[fkey * ATS];
                kdst[sperm64(d + 0)] = tff(kr[i].x);
                kdst[sperm64(d + 1)] = tff(kr[i].y);
                kdst[sperm64(d + 2)] = tff(kr[i].z);
                kdst[sperm64(d + 3)] = tff(kr[i].w);
                Vs[(d + 0) * ATS + spk] = tff(vr[i].x);
                Vs[(d + 1) * ATS + spk] = tff(vr[i].y);
                Vs[(d + 2) * ATS + spk] = tff(vr[i].z);
                Vs[(d + 3) * ATS + spk] = tff(vr[i].w);
            }
            __syncthreads();
        }
    }

    // ---- output: o / (l * 32) -> g_ao[b, n, head*64+d] ----
    const int b = bh >> 4, head = bh & 15;
    const int row0 = qt * 128 + w * 16 + g;
    float inv0 = 1.0f / (l0 * 32.0f);
    float inv1 = 1.0f / (l1 * 32.0f);
    float* dst0 = g_ao + ((size_t)b * NN + row0) * DD + head * HD;
    float* dst1 = dst0 + 8 * DD;
    #pragma unroll
    for (int nt = 0; nt < 8; nt++) {
        int d = nt * 8 + c2;
        *(float2*)&dst0[d] = make_float2(o[nt][0] * inv0, o[nt][1] * inv0);
        *(float2*)&dst1[d] = make_float2(o[nt][2] * inv1, o[nt][3] * inv1);
    }
}

// ================= gamma/beta GEMV =================
__global__ void __launch_bounds__(256) gammabeta_kernel(
    const float* __restrict__ w,  const float* __restrict__ Wg,
    const float* __restrict__ bg, const float* __restrict__ Wb,
    const float* __restrict__ bb)
{
    int lane = threadIdx.x & 31;
    int warp = threadIdx.x >> 5;
    int gid  = blockIdx.x * 8 + warp;
    int b = gid >> 10, d = gid & 1023;
    const float* wrow = w  + b * DD;
    const float* wg   = Wg + (size_t)d * DD;
    const float* wb   = Wb + (size_t)d * DD;
    float sg = 0.f, sb = 0.f;
    #pragma unroll 4
    for (int k = lane; k < DD; k += 32) {
        float wk = wrow[k];
        sg = fmaf(wk, wg[k], sg);
        sb = fmaf(wk, wb[k], sb);
    }
    #pragma unroll
    for (int o = 16; o; o >>= 1) {
        sg += __shfl_xor_sync(0xffffffffu, sg, o);
        sb += __shfl_xor_sync(0xffffffffu, sb, o);
    }
    if (!lane) {
        g_gamma[gid] = sg + bg[d];
        g_beta[gid]  = sb + bb[d];
    }
}

// ================= SLN kernels =================
__device__ __forceinline__ void row_stats(float4 xv, float& mu, float& rstd,
                                          float* red)
{
    float s = xv.x + xv.y + xv.z + xv.w;
    float q = xv.x*xv.x + xv.y*xv.y + xv.z*xv.z + xv.w*xv.w;
    #pragma unroll
    for (int o = 16; o; o >>= 1) {
        s += __shfl_xor_sync(0xffffffffu, s, o);
        q += __shfl_xor_sync(0xffffffffu, q, o);
    }
    int warp = threadIdx.x >> 5, lane = threadIdx.x & 31;
    if (!lane) { red[warp] = s; red[8 + warp] = q; }
    __syncthreads();
    float ss = 0.f, qq = 0.f;
    #pragma unroll
    for (int i = 0; i < 8; i++) { ss += red[i]; qq += red[8 + i]; }
    mu = ss * (1.0f / DD);
    float var = qq * (1.0f / DD) - mu * mu;
    rstd = rsqrtf(var + 1e-5f);
}

__global__ void __launch_bounds__(256) sln1_kernel(
    const float* __restrict__ x, const float* __restrict__ ln_g,
    const float* __restrict__ ln_b)
{
    __shared__ float red[16];
    int row = blockIdx.x;
    int b = row >> 10;
    float4 xv = *(const float4*)(x + (size_t)row * DD + threadIdx.x * 4);
    float mu, rstd;
    row_stats(xv, mu, rstd, red);
    int d = threadIdx.x * 4;
    float4 g  = *(const float4*)(ln_g + d);
    float4 lb = *(const float4*)(ln_b + d);
    float4 ga = *(const float4*)(g_gamma + b * DD + d);
    float4 be = *(const float4*)(g_beta  + b * DD + d);
    float4 y;
    y.x = fmaf(ga.x, fmaf((xv.x - mu) * rstd, g.x, lb.x), be.x);
    y.y = fmaf(ga.y, fmaf((xv.y - mu) * rstd, g.y, lb.y), be.y);
    y.z = fmaf(ga.z, fmaf((xv.z - mu) * rstd, g.z, lb.z), be.z);
    y.w = fmaf(ga.w, fmaf((xv.w - mu) * rstd, g.w, lb.w), be.w);
    *(float4*)&g_h[(size_t)row * DD + d] = y;
}

__global__ void __launch_bounds__(256) sln2_kernel(
    const float* __restrict__ ln_g, const float* __restrict__ ln_b,
    float* __restrict__ out)
{
    __shared__ float red[16];
    int row = blockIdx.x;
    int b = row >> 10;
    float4 xv = *(const float4*)(g_h1 + (size_t)row * DD + threadIdx.x * 4);
    float mu, rstd;
    row_stats(xv, mu, rstd, red);
    int d = threadIdx.x * 4;
    float4 g  = *(const float4*)(ln_g + d);
    float4 lb = *(const float4*)(ln_b + d);
    float4 ga = *(const float4*)(g_gamma + b * DD + d);
    float4 be = *(const float4*)(g_beta  + b * DD + d);
    float4 y;
    y.x = fmaf(ga.x, fmaf((xv.x - mu) * rstd, g.x, lb.x), be.x) + xv.x;
    y.y = fmaf(ga.y, fmaf((xv.y - mu) * rstd, g.y, lb.y), be.y) + xv.y;
    y.z = fmaf(ga.z, fmaf((xv.z - mu) * rstd, g.z, lb.z), be.z) + xv.z;
    y.w = fmaf(ga.w, fmaf((xv.w - mu) * rstd, g.w, lb.w), be.w) + xv.w;
    *(float4*)&out[(size_t)row * DD + d] = y;
}

// =====================================================================
extern "C" void kernel_launch(void* const* d_in, const int* in_sizes, int n_in,
                              void* d_out, int out_size)
{
    (void)in_sizes; (void)n_in; (void)out_size;
    const float* hidden = (const float*)d_in[0];
    const float* w      = (const float*)d_in[1];
    const float* ln_g   = (const float*)d_in[2];
    const float* ln_b   = (const float*)d_in[3];
    const float* Wg     = (const float*)d_in[4];
    const float* bg     = (const float*)d_in[5];
    const float* Wb     = (const float*)d_in[6];
    const float* bb     = (const float*)d_in[7];
    const float* Wqkv   = (const float*)d_in[8];
    const float* bqkv   = (const float*)d_in[9];
    const float* Wp     = (const float*)d_in[10];
    const float* bp     = (const float*)d_in[11];
    float* out = (float*)d_out;

    cudaFuncSetAttribute(attn_mma, cudaFuncAttributeMaxDynamicSharedMemorySize,
                         ATTN_SMEM_B);

    gammabeta_kernel<<<512, 256>>>(w, Wg, bg, Wb, bb);
    sln1_kernel<<<ROWS, 256>>>(hidden, ln_g, ln_b);
    mm_mma<1><<<dim3(QKVN / 128, ROWS / 128), 256>>>(Wqkv, bqkv, hidden);
    attn_mma<<<dim3(NN / 128, BB * HH), 256, ATTN_SMEM_B>>>();
    mm_mma<0><<<dim3(DD / 128, ROWS / 128), 256>>>(Wp, bp, hidden);
    sln2_kernel<<<ROWS, 256>>>(ln_g, ln_b, out);
}

// round 4
// speedup vs baseline: 2.3713x; 1.4759x over previous
#include <cuda_runtime.h>
#include <cstdint>

// ---------------- problem dims ----------------
#define BB 4
#define NN 1024
#define DD 1024
#define HH 16
#define HD 64
#define ROWS (BB*NN)      // 4096
#define QKVN (3*DD)       // 3072

// ---------------- scratch ----------------
__device__ float g_gamma[BB*DD];
__device__ float g_beta[BB*DD];
__device__ float g_h[ROWS*DD];
__device__ float g_q[BB*HH*NN*HD];
__device__ float g_k[BB*HH*NN*HD];
__device__ float g_v[BB*HH*NN*HD];
__device__ float g_ao[ROWS*DD];
__device__ float g_h1[ROWS*DD];

// ================= helpers =================
__device__ __forceinline__ uint32_t smem_u32(const void* p) {
    uint32_t a;
    asm("{ .reg .u64 t; cvta.to.shared.u64 t, %1; cvt.u32.u64 %0, t; }"
        : "=r"(a) : "l"(p));
    return a;
}
__device__ __forceinline__ void cp16(uint32_t dst, const void* src) {
    asm volatile("cp.async.cg.shared.global [%0], [%1], 16;"
                 :: "r"(dst), "l"(src) : "memory");
}
__device__ __forceinline__ void cp_commit() {
    asm volatile("cp.async.commit_group;" ::: "memory");
}
__device__ __forceinline__ void cp_wait0() {
    asm volatile("cp.async.wait_group 0;" ::: "memory");
}
// mma.tf32: raw fp32 bits in, HW uses top 19 bits (RZ truncation)
__device__ __forceinline__ void mma_tf32(float* d, const uint32_t* a,
                                         uint32_t b0, uint32_t b1) {
    asm volatile("mma.sync.aligned.m16n8k8.row.col.f32.tf32.tf32.f32 "
        "{%0,%1,%2,%3}, {%4,%5,%6,%7}, {%8,%9}, {%0,%1,%2,%3};"
        : "+f"(d[0]), "+f"(d[1]), "+f"(d[2]), "+f"(d[3])
        : "r"(a[0]), "r"(a[1]), "r"(a[2]), "r"(a[3]), "r"(b0), "r"(b1));
}

// =====================================================================
// GEMM via mma.sync tf32 + cp.async double buffer.
// C tile 128x128, K=1024 in 64 stages of 16. smem row stride 20 floats
// (80B = 5 x 16B, cp.async-aligned; lds.32 frag loads conflict-free).
// =====================================================================
#define MST 20

template<int QKV>
__global__ void __launch_bounds__(256, 2) mm_cp(
    const float* __restrict__ Bw, const float* __restrict__ bias,
    const float* __restrict__ resid)
{
    __shared__ float As[2][128 * MST];
    __shared__ float Bs[2][128 * MST];

    const int tid  = threadIdx.x;
    const int lane = tid & 31, wid = tid >> 5;
    const int bm = blockIdx.y * 128, bn = blockIdx.x * 128;
    const float* Asrc = QKV ? g_h : g_ao;

    // loader: row r = tid>>1, half hh = tid&1 -> floats hh*8 + {0,4}
    const int r  = tid >> 1;
    const int hh = tid & 1;
    const float* aptr = Asrc + (size_t)(bm + r) * DD + hh * 8;
    int j = bn + r;
    int bj = QKV ? (((j & 1023) >> 6) * 192 + (j & 63) * 3 + (j >> 10)) : j;
    const float* bptr = Bw + (size_t)bj * DD + hh * 8;
    const uint32_t sA0 = smem_u32(&As[0][r * MST + hh * 8]);
    const uint32_t sA1 = smem_u32(&As[1][r * MST + hh * 8]);
    const uint32_t sB0 = smem_u32(&Bs[0][r * MST + hh * 8]);
    const uint32_t sB1 = smem_u32(&Bs[1][r * MST + hh * 8]);

    // warp tile mapping
    const int wm = (wid & 1) * 64;
    const int wn = (wid >> 1) * 32;
    const int g  = lane >> 2;
    const int cc = lane & 3;
    const int c2 = cc * 2;

    float acc[4][4][4];
    #pragma unroll
    for (int mt = 0; mt < 4; mt++)
        #pragma unroll
        for (int nt = 0; nt < 4; nt++)
            #pragma unroll
            for (int e = 0; e < 4; e++) acc[mt][nt][e] = 0.f;

    // prologue: stage 0 -> buf 0
    cp16(sA0, aptr);      cp16(sA0 + 16, aptr + 4);
    cp16(sB0, bptr);      cp16(sB0 + 16, bptr + 4);
    cp_commit();

    for (int t = 0; t < 64; t++) {
        const int buf = t & 1;
        cp_wait0();
        __syncthreads();
        if (t < 63) {
            const float* ap = aptr + (t + 1) * 16;
            const float* bp = bptr + (t + 1) * 16;
            const uint32_t da = buf ? sA0 : sA1;
            const uint32_t db = buf ? sB0 : sB1;
            cp16(da, ap);      cp16(da + 16, ap + 4);
            cp16(db, bp);      cp16(db + 16, bp + 4);
            cp_commit();
        }
        const float* Ab = As[buf];
        const float* Bb = Bs[buf];
        #pragma unroll
        for (int kc = 0; kc < 2; kc++) {
            uint32_t af[4][4], bf[4][2];
            #pragma unroll
            for (int mt = 0; mt < 4; mt++) {
                const float* pa = Ab + (wm + mt * 16 + g) * MST + kc * 8 + cc;
                af[mt][0] = __float_as_uint(pa[0]);
                af[mt][1] = __float_as_uint(pa[8 * MST]);
                af[mt][2] = __float_as_uint(pa[4]);
                af[mt][3] = __float_as_uint(pa[8 * MST + 4]);
            }
            #pragma unroll
            for (int nt = 0; nt < 4; nt++) {
                const float* pb = Bb + (wn + nt * 8 + g) * MST + kc * 8 + cc;
                bf[nt][0] = __float_as_uint(pb[0]);
                bf[nt][1] = __float_as_uint(pb[4]);
            }
            #pragma unroll
            for (int mt = 0; mt < 4; mt++)
                #pragma unroll
                for (int nt = 0; nt < 4; nt++)
                    mma_tf32(acc[mt][nt], af[mt], bf[nt][0], bf[nt][1]);
        }
    }

    // ---- epilogue ----
    #pragma unroll
    for (int mt = 0; mt < 4; mt++) {
        #pragma unroll
        for (int nt = 0; nt < 4; nt++) {
            int R0 = bm + wm + mt * 16 + g;
            int C  = bn + wn + nt * 8 + c2;
            float v00 = acc[mt][nt][0], v01 = acc[mt][nt][1];
            float v10 = acc[mt][nt][2], v11 = acc[mt][nt][3];
            if (QKV) {
                int arr = C >> 10, rem = C & 1023;
                int head = rem >> 6, dd = rem & 63;
                float bx = bias[head * 192 + dd * 3 + arr];
                float by = bias[head * 192 + (dd + 1) * 3 + arr];
                float* dst = (arr == 0) ? g_q : (arr == 1) ? g_k : g_v;
                int b0 = R0 >> 10, n0 = R0 & 1023;
                size_t base = (((size_t)(b0 * HH + head)) * NN);
                *(float2*)&dst[(base + n0) * HD + dd] =
                    make_float2(v00 + bx, v01 + by);
                *(float2*)&dst[(base + n0 + 8) * HD + dd] =
                    make_float2(v10 + bx, v11 + by);
            } else {
                float2 bb = *(const float2*)(bias + C);
                float2 h0 = *(const float2*)(resid + (size_t)R0 * DD + C);
                float2 h1 = *(const float2*)(resid + (size_t)(R0 + 8) * DD + C);
                *(float2*)&g_h1[(size_t)R0 * DD + C] =
                    make_float2(v00 + bb.x + h0.x, v01 + bb.y + h0.y);
                *(float2*)&g_h1[(size_t)(R0 + 8) * DD + C] =
                    make_float2(v10 + bb.x + h1.x, v11 + bb.y + h1.y);
            }
        }
    }
}

// =====================================================================
// Flash attention via mma.sync tf32 + cp.async double-buffered K/V.
// 256 threads / 8 warps, 128 queries per CTA (16/warp), 16 key tiles of 64.
// Ks[buf][key][dim]  stride 68 (S B-frags conflict-free)
// Vs[buf][key][dim]  stride 72 (PV B-frags read k-major conflict-free)
// Ps[warp][16][68]   P staging (raw f32 bits -> tf32 truncation)
// =====================================================================
#define KST 68
#define VST 72
#define ATTN_SMEM_CP ((2*64*KST + 2*64*VST + 8*16*KST) * 4)   // 106496 B

__global__ void __launch_bounds__(256, 2) attn_cp()
{
    extern __shared__ float sf[];
    const int tid = threadIdx.x, lane = tid & 31, w = tid >> 5;
    const int g = lane >> 2, cc = lane & 3, c2 = cc * 2;
    const int bh = blockIdx.y, qt = blockIdx.x;

    float* Ks0 = sf;
    float* Vs0 = sf + 2 * 64 * KST;
    float* Ps  = sf + 2 * 64 * KST + 2 * 64 * VST + w * 16 * KST;

    const float* Qg = g_q + ((size_t)bh * NN + qt * 128 + w * 16) * HD;
    const float* Kg = g_k + (size_t)bh * NN * HD;
    const float* Vg = g_v + (size_t)bh * NN * HD;

    // loader mapping: row = tid>>2 (0..63), cols 16*(tid&3) + {0,4,8,12}
    const int lrow = tid >> 2;
    const int lcol = (tid & 3) * 16;
    const float* kpb = Kg + lrow * HD + lcol;
    const float* vpb = Vg + lrow * HD + lcol;
    const uint32_t skb = smem_u32(Ks0 + lrow * KST + lcol);
    const uint32_t svb = smem_u32(Vs0 + lrow * VST + lcol);
    const uint32_t kstep = 64 * KST * 4;
    const uint32_t vstep = 64 * VST * 4;

    // prologue: tile 0 -> buf 0
    #pragma unroll
    for (int i = 0; i < 4; i++) {
        cp16(skb + i * 16, kpb + i * 4);
        cp16(svb + i * 16, vpb + i * 4);
    }
    cp_commit();

    // Q fragments (raw fp32 bits), resident for the whole kernel
    uint32_t qf[8][4];
    #pragma unroll
    for (int kc = 0; kc < 8; kc++) {
        qf[kc][0] = __float_as_uint(Qg[g * HD + kc * 8 + cc]);
        qf[kc][1] = __float_as_uint(Qg[(g + 8) * HD + kc * 8 + cc]);
        qf[kc][2] = __float_as_uint(Qg[g * HD + kc * 8 + cc + 4]);
        qf[kc][3] = __float_as_uint(Qg[(g + 8) * HD + kc * 8 + cc + 4]);
    }

    float o[8][4];
    #pragma unroll
    for (int nt = 0; nt < 8; nt++)
        #pragma unroll
        for (int e = 0; e < 4; e++) o[nt][e] = 0.f;
    float m0 = -1e30f, m1 = -1e30f, l0 = 0.f, l1 = 0.f;

    for (int t = 0; t < 16; t++) {
        const int buf = t & 1;
        const float* Kbuf = Ks0 + buf * 64 * KST;
        const float* Vbuf = Vs0 + buf * 64 * VST;

        cp_wait0();
        __syncthreads();
        if (t < 15) {
            const float* kp = kpb + (size_t)(t + 1) * 64 * HD;
            const float* vp = vpb + (size_t)(t + 1) * 64 * HD;
            const uint32_t sk = skb + (buf ^ 1) * kstep;
            const uint32_t sv = svb + (buf ^ 1) * vstep;
            #pragma unroll
            for (int i = 0; i < 4; i++) {
                cp16(sk + i * 16, kp + i * 4);
                cp16(sv + i * 16, vp + i * 4);
            }
            cp_commit();
        }

        // ---- S = Q K^T ----
        float s[8][4];
        #pragma unroll
        for (int nt = 0; nt < 8; nt++) {
            s[nt][0] = s[nt][1] = s[nt][2] = s[nt][3] = 0.f;
            #pragma unroll
            for (int kc = 0; kc < 8; kc++) {
                const float* pk = Kbuf + (nt * 8 + g) * KST + kc * 8 + cc;
                mma_tf32(s[nt], qf[kc],
                         __float_as_uint(pk[0]), __float_as_uint(pk[4]));
            }
        }

        // ---- online softmax ----
        float rmax0 = -1e30f, rmax1 = -1e30f;
        #pragma unroll
        for (int nt = 0; nt < 8; nt++) {
            rmax0 = fmaxf(rmax0, fmaxf(s[nt][0], s[nt][1]));
            rmax1 = fmaxf(rmax1, fmaxf(s[nt][2], s[nt][3]));
        }
        rmax0 = fmaxf(rmax0, __shfl_xor_sync(0xffffffffu, rmax0, 1));
        rmax0 = fmaxf(rmax0, __shfl_xor_sync(0xffffffffu, rmax0, 2));
        rmax1 = fmaxf(rmax1, __shfl_xor_sync(0xffffffffu, rmax1, 1));
        rmax1 = fmaxf(rmax1, __shfl_xor_sync(0xffffffffu, rmax1, 2));
        float mn0 = fmaxf(m0, rmax0), mn1 = fmaxf(m1, rmax1);
        float sc0 = __expf(m0 - mn0), sc1 = __expf(m1 - mn1);
        m0 = mn0; m1 = mn1;
        float rs0 = 0.f, rs1 = 0.f;
        #pragma unroll
        for (int nt = 0; nt < 8; nt++) {
            s[nt][0] = __expf(s[nt][0] - mn0); rs0 += s[nt][0];
            s[nt][1] = __expf(s[nt][1] - mn0); rs0 += s[nt][1];
            s[nt][2] = __expf(s[nt][2] - mn1); rs1 += s[nt][2];
            s[nt][3] = __expf(s[nt][3] - mn1); rs1 += s[nt][3];
        }
        rs0 += __shfl_xor_sync(0xffffffffu, rs0, 1);
        rs0 += __shfl_xor_sync(0xffffffffu, rs0, 2);
        rs1 += __shfl_xor_sync(0xffffffffu, rs1, 1);
        rs1 += __shfl_xor_sync(0xffffffffu, rs1, 2);
        l0 = l0 * sc0 + rs0;
        l1 = l1 * sc1 + rs1;
        #pragma unroll
        for (int nt = 0; nt < 8; nt++) {
            o[nt][0] *= sc0; o[nt][1] *= sc0;
            o[nt][2] *= sc1; o[nt][3] *= sc1;
        }

        // ---- stage P (raw bits) ----
        #pragma unroll
        for (int nt = 0; nt < 8; nt++) {
            *(float2*)&Ps[g * KST + nt * 8 + c2] = make_float2(s[nt][0], s[nt][1]);
            *(float2*)&Ps[(g + 8) * KST + nt * 8 + c2] = make_float2(s[nt][2], s[nt][3]);
        }
        __syncwarp();

        // ---- O += P V ----
        #pragma unroll
        for (int kc = 0; kc < 8; kc++) {
            uint32_t pa[4];
            pa[0] = __float_as_uint(Ps[g * KST + kc * 8 + cc]);
            pa[1] = __float_as_uint(Ps[(g + 8) * KST + kc * 8 + cc]);
            pa[2] = __float_as_uint(Ps[g * KST + kc * 8 + cc + 4]);
            pa[3] = __float_as_uint(Ps[(g + 8) * KST + kc * 8 + cc + 4]);
            #pragma unroll
            for (int nt = 0; nt < 8; nt++) {
                float b0 = Vbuf[(kc * 8 + cc) * VST + nt * 8 + g];
                float b1 = Vbuf[(kc * 8 + cc + 4) * VST + nt * 8 + g];
                mma_tf32(o[nt], pa, __float_as_uint(b0), __float_as_uint(b1));
            }
        }
    }

    // ---- output: o / (l * 32) ----
    const int b = bh >> 4, head = bh & 15;
    const int row0 = qt * 128 + w * 16 + g;
    float inv0 = 1.0f / (l0 * 32.0f);
    float inv1 = 1.0f / (l1 * 32.0f);
    float* dst0 = g_ao + ((size_t)b * NN + row0) * DD + head * HD;
    float* dst1 = dst0 + 8 * DD;
    #pragma unroll
    for (int nt = 0; nt < 8; nt++) {
        int d = nt * 8 + c2;
        *(float2*)&dst0[d] = make_float2(o[nt][0] * inv0, o[nt][1] * inv0);
        *(float2*)&dst1[d] = make_float2(o[nt][2] * inv1, o[nt][3] * inv1);
    }
}

// ================= gamma/beta GEMV (float4) =================
__global__ void __launch_bounds__(256) gammabeta_kernel(
    const float* __restrict__ w,  const float* __restrict__ Wg,
    const float* __restrict__ bg, const float* __restrict__ Wb,
    const float* __restrict__ bb)
{
    int lane = threadIdx.x & 31;
    int warp = threadIdx.x >> 5;
    int gid  = blockIdx.x * 8 + warp;
    int b = gid >> 10, d = gid & 1023;
    const float* wrow = w  + b * DD;
    const float* wg   = Wg + (size_t)d * DD;
    const float* wb   = Wb + (size_t)d * DD;
    float sg = 0.f, sb = 0.f;
    #pragma unroll
    for (int it = 0; it < 8; it++) {
        int k = it * 128 + lane * 4;
        float4 wk = *(const float4*)(wrow + k);
        float4 a  = *(const float4*)(wg + k);
        float4 c  = *(const float4*)(wb + k);
        sg = fmaf(wk.x, a.x, fmaf(wk.y, a.y, fmaf(wk.z, a.z, fmaf(wk.w, a.w, sg))));
        sb = fmaf(wk.x, c.x, fmaf(wk.y, c.y, fmaf(wk.z, c.z, fmaf(wk.w, c.w, sb))));
    }
    #pragma unroll
    for (int o = 16; o; o >>= 1) {
        sg += __shfl_xor_sync(0xffffffffu, sg, o);
        sb += __shfl_xor_sync(0xffffffffu, sb, o);
    }
    if (!lane) {
        g_gamma[gid] = sg + bg[d];
        g_beta[gid]  = sb + bb[d];
    }
}

// ================= SLN kernels =================
__device__ __forceinline__ void row_stats(float4 xv, float& mu, float& rstd,
                                          float* red)
{
    float s = xv.x + xv.y + xv.z + xv.w;
    float q = xv.x*xv.x + xv.y*xv.y + xv.z*xv.z + xv.w*xv.w;
    #pragma unroll
    for (int o = 16; o; o >>= 1) {
        s += __shfl_xor_sync(0xffffffffu, s, o);
        q += __shfl_xor_sync(0xffffffffu, q, o);
    }
    int warp = threadIdx.x >> 5, lane = threadIdx.x & 31;
    if (!lane) { red[warp] = s; red[8 + warp] = q; }
    __syncthreads();
    float ss = 0.f, qq = 0.f;
    #pragma unroll
    for (int i = 0; i < 8; i++) { ss += red[i]; qq += red[8 + i]; }
    mu = ss * (1.0f / DD);
    float var = qq * (1.0f / DD) - mu * mu;
    rstd = rsqrtf(var + 1e-5f);
}

__global__ void __launch_bounds__(256) sln1_kernel(
    const float* __restrict__ x, const float* __restrict__ ln_g,
    const float* __restrict__ ln_b)
{
    __shared__ float red[16];
    int row = blockIdx.x;
    int b = row >> 10;
    float4 xv = *(const float4*)(x + (size_t)row * DD + threadIdx.x * 4);
    float mu, rstd;
    row_stats(xv, mu, rstd, red);
    int d = threadIdx.x * 4;
    float4 g  = *(const float4*)(ln_g + d);
    float4 lb = *(const float4*)(ln_b + d);
    float4 ga = *(const float4*)(g_gamma + b * DD + d);
    float4 be = *(const float4*)(g_beta  + b * DD + d);
    float4 y;
    y.x = fmaf(ga.x, fmaf((xv.x - mu) * rstd, g.x, lb.x), be.x);
    y.y = fmaf(ga.y, fmaf((xv.y - mu) * rstd, g.y, lb.y), be.y);
    y.z = fmaf(ga.z, fmaf((xv.z - mu) * rstd, g.z, lb.z), be.z);
    y.w = fmaf(ga.w, fmaf((xv.w - mu) * rstd, g.w, lb.w), be.w);
    *(float4*)&g_h[(size_t)row * DD + d] = y;
}

__global__ void __launch_bounds__(256) sln2_kernel(
    const float* __restrict__ ln_g, const float* __restrict__ ln_b,
    float* __restrict__ out)
{
    __shared__ float red[16];
    int row = blockIdx.x;
    int b = row >> 10;
    float4 xv = *(const float4*)(g_h1 + (size_t)row * DD + threadIdx.x * 4);
    float mu, rstd;
    row_stats(xv, mu, rstd, red);
    int d = threadIdx.x * 4;
    float4 g  = *(const float4*)(ln_g + d);
    float4 lb = *(const float4*)(ln_b + d);
    float4 ga = *(const float4*)(g_gamma + b * DD + d);
    float4 be = *(const float4*)(g_beta  + b * DD + d);
    float4 y;
    y.x = fmaf(ga.x, fmaf((xv.x - mu) * rstd, g.x, lb.x), be.x) + xv.x;
    y.y = fmaf(ga.y, fmaf((xv.y - mu) * rstd, g.y, lb.y), be.y) + xv.y;
    y.z = fmaf(ga.z, fmaf((xv.z - mu) * rstd, g.z, lb.z), be.z) + xv.z;
    y.w = fmaf(ga.w, fmaf((xv.w - mu) * rstd, g.w, lb.w), be.w) + xv.w;
    *(float4*)&out[(size_t)row * DD + d] = y;
}

// =====================================================================
extern "C" void kernel_launch(void* const* d_in, const int* in_sizes, int n_in,
                              void* d_out, int out_size)
{
    (void)in_sizes; (void)n_in; (void)out_size;
    const float* hidden = (const float*)d_in[0];
    const float* w      = (const float*)d_in[1];
    const float* ln_g   = (const float*)d_in[2];
    const float* ln_b   = (const float*)d_in[3];
    const float* Wg     = (const float*)d_in[4];
    const float* bg     = (const float*)d_in[5];
    const float* Wb     = (const float*)d_in[6];
    const float* bb     = (const float*)d_in[7];
    const float* Wqkv   = (const float*)d_in[8];
    const float* bqkv   = (const float*)d_in[9];
    const float* Wp     = (const float*)d_in[10];
    const float* bp     = (const float*)d_in[11];
    float* out = (float*)d_out;

    cudaFuncSetAttribute(attn_cp, cudaFuncAttributeMaxDynamicSharedMemorySize,
                         ATTN_SMEM_CP);

    gammabeta_kernel<<<512, 256>>>(w, Wg, bg, Wb, bb);
    sln1_kernel<<<ROWS, 256>>>(hidden, ln_g, ln_b);
    mm_cp<1><<<dim3(QKVN / 128, ROWS / 128), 256>>>(Wqkv, bqkv, hidden);
    attn_cp<<<dim3(NN / 128, BB * HH), 256, ATTN_SMEM_CP>>>();
    mm_cp<0><<<dim3(DD / 128, ROWS / 128), 256>>>(Wp, bp, hidden);
    sln2_kernel<<<ROWS, 256>>>(ln_g, ln_b, out);
}

// round 6
// speedup vs baseline: 4.3446x; 1.8321x over previous
#include <cuda_runtime.h>
#include <cstdint>

// ---------------- problem dims ----------------
#define BB 4
#define NN 1024
#define DD 1024
#define HH 16
#define HD 64
#define ROWS (BB*NN)      // 4096
#define QKVN (3*DD)       // 3072

// ---------------- scratch ----------------
__device__ float    g_gamma[BB*DD];
__device__ float    g_beta[BB*DD];
__device__ uint16_t g_hb[ROWS*DD];          // SLN(hidden), bf16
__device__ uint16_t g_wqkvb[QKVN*DD];       // Wqkv bf16, pre-permuted rows
__device__ uint16_t g_wpb[DD*DD];           // Wp bf16
__device__ uint16_t g_qb[BB*HH*NN*HD];      // [bh][n][d]
__device__ uint16_t g_kb[BB*HH*NN*HD];      // [bh][n][d]
__device__ uint16_t g_vtb[BB*HH*HD*NN];     // [bh][d][n]  (transposed V)
__device__ uint16_t g_aob[ROWS*DD];         // attention out bf16
__device__ float    g_h1[ROWS*DD];

// ================= helpers =================
__device__ __forceinline__ uint32_t smem_u32(const void* p) {
    uint32_t a;
    asm("{ .reg .u64 t; cvta.to.shared.u64 t, %1; cvt.u32.u64 %0, t; }"
        : "=r"(a) : "l"(p));
    return a;
}
__device__ __forceinline__ void cp16(uint32_t dst, const void* src) {
    asm volatile("cp.async.cg.shared.global [%0], [%1], 16;"
                 :: "r"(dst), "l"(src) : "memory");
}
__device__ __forceinline__ void cp_commit() {
    asm volatile("cp.async.commit_group;" ::: "memory");
}
template<int N>
__device__ __forceinline__ void cp_wait() {
    asm volatile("cp.async.wait_group %0;" :: "n"(N) : "memory");
}
// pack two f32 -> bf16x2 (lo = first arg at lower address)
__device__ __forceinline__ uint32_t pbf2(float lo, float hi) {
    uint32_t r;
    asm("cvt.rn.bf16x2.f32 %0, %1, %2;" : "=r"(r) : "f"(hi), "f"(lo));
    return r;
}
__device__ __forceinline__ uint16_t bf1(float x) {
    uint16_t r; asm("cvt.rn.bf16.f32 %0, %1;" : "=h"(r) : "f"(x)); return r;
}
__device__ __forceinline__ void mma_bf16(float* d, const uint32_t* a,
                                         uint32_t b0, uint32_t b1) {
    asm volatile("mma.sync.aligned.m16n8k16.row.col.f32.bf16.bf16.f32 "
        "{%0,%1,%2,%3}, {%4,%5,%6,%7}, {%8,%9}, {%0,%1,%2,%3};"
        : "+f"(d[0]), "+f"(d[1]), "+f"(d[2]), "+f"(d[3])
        : "r"(a[0]), "r"(a[1]), "r"(a[2]), "r"(a[3]), "r"(b0), "r"(b1));
}

// ================= weight conversion (per-launch, deterministic) =======
__global__ void __launch_bounds__(256) convert_wqkv(const float* __restrict__ W)
{
    int e = (blockIdx.x * 256 + threadIdx.x) * 4;     // over 3072*1024
    int j = e >> 10, k = e & 1023;
    int pj = ((j & 1023) >> 6) * 192 + (j & 63) * 3 + (j >> 10);
    float4 v = *(const float4*)(W + (size_t)pj * DD + k);
    *(uint2*)(g_wqkvb + e) = make_uint2(pbf2(v.x, v.y), pbf2(v.z, v.w));
}
__global__ void __launch_bounds__(256) convert_wp(const float* __restrict__ W)
{
    int e = (blockIdx.x * 256 + threadIdx.x) * 4;     // over 1024*1024
    float4 v = *(const float4*)(W + e);
    *(uint2*)(g_wpb + e) = make_uint2(pbf2(v.x, v.y), pbf2(v.z, v.w));
}

// =====================================================================
// bf16 GEMM via mma.m16n8k16 + 3-stage cp.async ring.
// C tile 128x128, K=1024 in 32 stages of 32. smem row 40 bf16 (80B),
// fragment lds.32 conflict-free: bank = (20g + 8kc + cc) mod 32 distinct.
// =====================================================================
#define MSTB 40
#define MM_STAGE (128 * MSTB)                 // uint16 elems per matrix stage
#define MM_DSMEM (6 * MM_STAGE * 2)           // 61440 bytes

template<int QKV>
__global__ void __launch_bounds__(256, 2) mm_bf(
    const float* __restrict__ bias, const float* __restrict__ resid)
{
    extern __shared__ uint16_t smb[];
    uint16_t* Abuf = smb;                     // [3][128*40]
    uint16_t* Bbuf = smb + 3 * MM_STAGE;

    const int tid = threadIdx.x, lane = tid & 31, wid = tid >> 5;
    const int bm = blockIdx.y * 128, bn = blockIdx.x * 128;
    const uint16_t* Asrc = QKV ? g_hb : g_aob;
    const uint16_t* Bsrc = QKV ? g_wqkvb : g_wpb;

    // loader: row r = tid>>1, half hh = tid&1 (32B each)
    const int r = tid >> 1, hh = tid & 1;
    const uint16_t* aptr = Asrc + (size_t)(bm + r) * DD + hh * 16;
    const uint16_t* bptr = Bsrc + (size_t)(bn + r) * DD + hh * 16;
    uint32_t sA[3], sB[3];
    #pragma unroll
    for (int s = 0; s < 3; s++) {
        sA[s] = smem_u32(Abuf + s * MM_STAGE + r * MSTB + hh * 16);
        sB[s] = smem_u32(Bbuf + s * MM_STAGE + r * MSTB + hh * 16);
    }

    const int wm = (wid & 1) * 64, wn = (wid >> 1) * 32;
    const int g = lane >> 2, cc = lane & 3, c2 = cc * 2;

    float acc[4][4][4];
    #pragma unroll
    for (int mt = 0; mt < 4; mt++)
        #pragma unroll
        for (int nt = 0; nt < 4; nt++)
            #pragma unroll
            for (int e = 0; e < 4; e++) acc[mt][nt][e] = 0.f;

    // prologue: stages 0,1
    #pragma unroll
    for (int s = 0; s < 2; s++) {
        cp16(sA[s], aptr + s * 32);  cp16(sA[s] + 16, aptr + s * 32 + 8);
        cp16(sB[s], bptr + s * 32);  cp16(sB[s] + 16, bptr + s * 32 + 8);
        cp_commit();
    }

    for (int t = 0; t < 32; t++) {
        const int buf = t % 3;
        if (t < 30) cp_wait<1>(); else cp_wait<0>();
        __syncthreads();
        if (t + 2 < 32) {
            const int s = (t + 2) % 3;
            const uint16_t* ap = aptr + (t + 2) * 32;
            const uint16_t* bp = bptr + (t + 2) * 32;
            cp16(sA[s], ap);  cp16(sA[s] + 16, ap + 8);
            cp16(sB[s], bp);  cp16(sB[s] + 16, bp + 8);
            cp_commit();
        }
        const uint32_t* Ab = (const uint32_t*)(Abuf + buf * MM_STAGE);
        const uint32_t* Bb = (const uint32_t*)(Bbuf + buf * MM_STAGE);
        #pragma unroll
        for (int kc = 0; kc < 2; kc++) {
            uint32_t af[4][4], bfr[4][2];
            #pragma unroll
            for (int mt = 0; mt < 4; mt++) {
                int base = (wm + mt * 16 + g) * 20 + kc * 8 + cc;
                af[mt][0] = Ab[base];
                af[mt][1] = Ab[base + 8 * 20];
                af[mt][2] = Ab[base + 4];
                af[mt][3] = Ab[base + 8 * 20 + 4];
            }
            #pragma unroll
            for (int nt = 0; nt < 4; nt++) {
                int base = (wn + nt * 8 + g) * 20 + kc * 8 + cc;
                bfr[nt][0] = Bb[base];
                bfr[nt][1] = Bb[base + 4];
            }
            #pragma unroll
            for (int mt = 0; mt < 4; mt++)
                #pragma unroll
                for (int nt = 0; nt < 4; nt++)
                    mma_bf16(acc[mt][nt], af[mt], bfr[nt][0], bfr[nt][1]);
        }
    }

    // ---- epilogue ----
    #pragma unroll
    for (int mt = 0; mt < 4; mt++) {
        #pragma unroll
        for (int nt = 0; nt < 4; nt++) {
            int R0 = bm + wm + mt * 16 + g;
            int C  = bn + wn + nt * 8 + c2;
            float v00 = acc[mt][nt][0], v01 = acc[mt][nt][1];
            float v10 = acc[mt][nt][2], v11 = acc[mt][nt][3];
            if (QKV) {
                int arr = C >> 10, rem = C & 1023;
                int head = rem >> 6, dd = rem & 63;
                float bx = bias[head * 192 + dd * 3 + arr];
                float by = bias[head * 192 + (dd + 1) * 3 + arr];
                int b0 = R0 >> 10, n0 = R0 & 1023;
                if (arr < 2) {
                    uint16_t* dst = arr ? g_kb : g_qb;
                    size_t base = ((size_t)(b0 * HH + head)) * NN;
                    *(uint32_t*)(dst + (base + n0) * HD + dd) =
                        pbf2(v00 + bx, v01 + by);
                    *(uint32_t*)(dst + (base + n0 + 8) * HD + dd) =
                        pbf2(v10 + bx, v11 + by);
                } else {
                    size_t vb = ((size_t)(b0 * HH + head)) * HD;
                    g_vtb[(vb + dd)     * NN + n0]     = bf1(v00 + bx);
                    g_vtb[(vb + dd + 1) * NN + n0]     = bf1(v01 + by);
                    g_vtb[(vb + dd)     * NN + n0 + 8] = bf1(v10 + bx);
                    g_vtb[(vb + dd + 1) * NN + n0 + 8] = bf1(v11 + by);
                }
            } else {
                float2 bb = *(const float2*)(bias + C);
                float2 h0 = *(const float2*)(resid + (size_t)R0 * DD + C);
                float2 h1 = *(const float2*)(resid + (size_t)(R0 + 8) * DD + C);
                *(float2*)&g_h1[(size_t)R0 * DD + C] =
                    make_float2(v00 + bb.x + h0.x, v01 + bb.y + h0.y);
                *(float2*)&g_h1[(size_t)(R0 + 8) * DD + C] =
                    make_float2(v10 + bb.x + h1.x, v11 + bb.y + h1.y);
            }
        }
    }
}

// =====================================================================
// Flash attention, bf16 m16n8k16. 8 warps, 128 queries/CTA, key tiles 64.
// Ks[buf][key][dim]  stride 72 bf16 (rows 144B; frag banks distinct)
// Vt[buf][dim][key]  stride 72 (V pre-transposed in gmem -> cp.async direct)
// P: S C-fragment == PV A-fragment layout -> reg->reg bf16 pack, no smem.
// =====================================================================
__global__ void __launch_bounds__(256, 2) attn_bf()
{
    __shared__ uint16_t Ks[2][64 * 72];
    __shared__ uint16_t Vt[2][64 * 72];

    const int tid = threadIdx.x, lane = tid & 31, w = tid >> 5;
    const int g = lane >> 2, cc = lane & 3, c2 = cc * 2;
    const int bh = blockIdx.y, qt = blockIdx.x;

    const uint16_t* Kg = g_kb + (size_t)bh * NN * HD;
    const uint16_t* Vg = g_vtb + (size_t)bh * HD * NN;

    // loader: 4 threads/row, 32B each
    const int lrow = tid >> 2;
    const int lcq  = (tid & 3) * 16;
    const uint16_t* kpb = Kg + lrow * HD + lcq;
    const uint16_t* vpb = Vg + (size_t)lrow * NN + lcq;
    uint32_t skb[2], svb[2];
    skb[0] = smem_u32(&Ks[0][lrow * 72 + lcq]);
    skb[1] = smem_u32(&Ks[1][lrow * 72 + lcq]);
    svb[0] = smem_u32(&Vt[0][lrow * 72 + lcq]);
    svb[1] = smem_u32(&Vt[1][lrow * 72 + lcq]);

    // prologue: tile 0 -> buf 0
    cp16(skb[0], kpb);  cp16(skb[0] + 16, kpb + 8);
    cp16(svb[0], vpb);  cp16(svb[0] + 16, vpb + 8);
    cp_commit();

    // Q fragments (bf16), resident
    const uint32_t* Qg32 =
        (const uint32_t*)(g_qb + ((size_t)bh * NN + qt * 128 + w * 16) * HD);
    uint32_t qf[4][4];
    #pragma unroll
    for (int kc = 0; kc < 4; kc++) {
        qf[kc][0] = Qg32[g * 32 + kc * 8 + cc];
        qf[kc][1] = Qg32[(g + 8) * 32 + kc * 8 + cc];
        qf[kc][2] = Qg32[g * 32 + kc * 8 + cc + 4];
        qf[kc][3] = Qg32[(g + 8) * 32 + kc * 8 + cc + 4];
    }

    float o[8][4];
    #pragma unroll
    for (int nt = 0; nt < 8; nt++)
        #pragma unroll
        for (int e = 0; e < 4; e++) o[nt][e] = 0.f;
    float m0 = -1e30f, m1 = -1e30f, l0 = 0.f, l1 = 0.f;

    for (int t = 0; t < 16; t++) {
        const int buf = t & 1;
        cp_wait<0>();
        __syncthreads();
        if (t < 15) {
            const uint16_t* kp = kpb + (size_t)(t + 1) * 64 * HD;
            const uint16_t* vp = vpb + (t + 1) * 64;
            cp16(skb[buf ^ 1], kp);  cp16(skb[buf ^ 1] + 16, kp + 8);
            cp16(svb[buf ^ 1], vp);  cp16(svb[buf ^ 1] + 16, vp + 8);
            cp_commit();
        }
        const uint32_t* Kb = (const uint32_t*)Ks[buf];
        const uint32_t* Vb = (const uint32_t*)Vt[buf];

        // ---- S = Q K^T ----
        float s[8][4];
        #pragma unroll
        for (int nt = 0; nt < 8; nt++) {
            s[nt][0] = s[nt][1] = s[nt][2] = s[nt][3] = 0.f;
            #pragma unroll
            for (int kc = 0; kc < 4; kc++) {
                int bi = (nt * 8 + g) * 36 + kc * 8 + cc;
                mma_bf16(s[nt], qf[kc], Kb[bi], Kb[bi + 4]);
            }
        }

        // ---- online softmax ----
        float rmax0 = -1e30f, rmax1 = -1e30f;
        #pragma unroll
        for (int nt = 0; nt < 8; nt++) {
            rmax0 = fmaxf(rmax0, fmaxf(s[nt][0], s[nt][1]));
            rmax1 = fmaxf(rmax1, fmaxf(s[nt][2], s[nt][3]));
        }
        rmax0 = fmaxf(rmax0, __shfl_xor_sync(0xffffffffu, rmax0, 1));
        rmax0 = fmaxf(rmax0, __shfl_xor_sync(0xffffffffu, rmax0, 2));
        rmax1 = fmaxf(rmax1, __shfl_xor_sync(0xffffffffu, rmax1, 1));
        rmax1 = fmaxf(rmax1, __shfl_xor_sync(0xffffffffu, rmax1, 2));
        float mn0 = fmaxf(m0, rmax0), mn1 = fmaxf(m1, rmax1);
        float sc0 = __expf(m0 - mn0), sc1 = __expf(m1 - mn1);
        m0 = mn0; m1 = mn1;
        float rs0 = 0.f, rs1 = 0.f;
        #pragma unroll
        for (int nt = 0; nt < 8; nt++) {
            s[nt][0] = __expf(s[nt][0] - mn0); rs0 += s[nt][0];
            s[nt][1] = __expf(s[nt][1] - mn0); rs0 += s[nt][1];
            s[nt][2] = __expf(s[nt][2] - mn1); rs1 += s[nt][2];
            s[nt][3] = __expf(s[nt][3] - mn1); rs1 += s[nt][3];
        }
        rs0 += __shfl_xor_sync(0xffffffffu, rs0, 1);
        rs0 += __shfl_xor_sync(0xffffffffu, rs0, 2);
        rs1 += __shfl_xor_sync(0xffffffffu, rs1, 1);
        rs1 += __shfl_xor_sync(0xffffffffu, rs1, 2);
        l0 = l0 * sc0 + rs0;
        l1 = l1 * sc1 + rs1;
        #pragma unroll
        for (int nt = 0; nt < 8; nt++) {
            o[nt][0] *= sc0; o[nt][1] *= sc0;
            o[nt][2] *= sc1; o[nt][3] *= sc1;
        }

        // ---- P: C-frag -> bf16 A-frag (register-only) ----
        uint32_t pa[4][4];
        #pragma unroll
        for (int kc = 0; kc < 4; kc++) {
            pa[kc][0] = pbf2(s[2 * kc][0],     s[2 * kc][1]);
            pa[kc][1] = pbf2(s[2 * kc][2],     s[2 * kc][3]);
            pa[kc][2] = pbf2(s[2 * kc + 1][0], s[2 * kc + 1][1]);
            pa[kc][3] = pbf2(s[2 * kc + 1][2], s[2 * kc + 1][3]);
        }

        // ---- O += P V ----
        #pragma unroll
        for (int kc = 0; kc < 4; kc++)
            #pragma unroll
            for (int nt = 0; nt < 8; nt++) {
                int bi = (nt * 8 + g) * 36 + kc * 8 + cc;
                mma_bf16(o[nt], pa[kc], Vb[bi], Vb[bi + 4]);
            }
    }

    // ---- output: bf16(o / (l * 32)) -> g_aob ----
    const int b = bh >> 4, head = bh & 15;
    const int row0 = qt * 128 + w * 16 + g;
    float inv0 = 1.0f / (l0 * 32.0f);
    float inv1 = 1.0f / (l1 * 32.0f);
    uint32_t* d0 = (uint32_t*)(g_aob + ((size_t)b * NN + row0) * DD + head * HD);
    uint32_t* d1 = (uint32_t*)(g_aob + ((size_t)b * NN + row0 + 8) * DD + head * HD);
    #pragma unroll
    for (int nt = 0; nt < 8; nt++) {
        d0[nt * 4 + cc] = pbf2(o[nt][0] * inv0, o[nt][1] * inv0);
        d1[nt * 4 + cc] = pbf2(o[nt][2] * inv1, o[nt][3] * inv1);
    }
}

// ================= gamma/beta GEMV (float4) =================
__global__ void __launch_bounds__(256) gammabeta_kernel(
    const float* __restrict__ w,  const float* __restrict__ Wg,
    const float* __restrict__ bg, const float* __restrict__ Wb,
    const float* __restrict__ bb)
{
    int lane = threadIdx.x & 31;
    int warp = threadIdx.x >> 5;
    int gid  = blockIdx.x * 8 + warp;
    int b = gid >> 10, d = gid & 1023;
    const float* wrow = w  + b * DD;
    const float* wg   = Wg + (size_t)d * DD;
    const float* wb   = Wb + (size_t)d * DD;
    float sg = 0.f, sb = 0.f;
    #pragma unroll
    for (int it = 0; it < 8; it++) {
        int k = it * 128 + lane * 4;
        float4 wk = *(const float4*)(wrow + k);
        float4 a  = *(const float4*)(wg + k);
        float4 c  = *(const float4*)(wb + k);
        sg = fmaf(wk.x, a.x, fmaf(wk.y, a.y, fmaf(wk.z, a.z, fmaf(wk.w, a.w, sg))));
        sb = fmaf(wk.x, c.x, fmaf(wk.y, c.y, fmaf(wk.z, c.z, fmaf(wk.w, c.w, sb))));
    }
    #pragma unroll
    for (int o = 16; o; o >>= 1) {
        sg += __shfl_xor_sync(0xffffffffu, sg, o);
        sb += __shfl_xor_sync(0xffffffffu, sb, o);
    }
    if (!lane) {
        g_gamma[gid] = sg + bg[d];
        g_beta[gid]  = sb + bb[d];
    }
}

// ================= SLN kernels =================
__device__ __forceinline__ void row_stats(float4 xv, float& mu, float& rstd,
                                          float* red)
{
    float s = xv.x + xv.y + xv.z + xv.w;
    float q = xv.x*xv.x + xv.y*xv.y + xv.z*xv.z + xv.w*xv.w;
    #pragma unroll
    for (int o = 16; o; o >>= 1) {
        s += __shfl_xor_sync(0xffffffffu, s, o);
        q += __shfl_xor_sync(0xffffffffu, q, o);
    }
    int warp = threadIdx.x >> 5, lane = threadIdx.x & 31;
    if (!lane) { red[warp] = s; red[8 + warp] = q; }
    __syncthreads();
    float ss = 0.f, qq = 0.f;
    #pragma unroll
    for (int i = 0; i < 8; i++) { ss += red[i]; qq += red[8 + i]; }
    mu = ss * (1.0f / DD);
    float var = qq * (1.0f / DD) - mu * mu;
    rstd = rsqrtf(var + 1e-5f);
}

__global__ void __launch_bounds__(256) sln1_kernel(
    const float* __restrict__ x, const float* __restrict__ ln_g,
    const float* __restrict__ ln_b)
{
    __shared__ float red[16];
    int row = blockIdx.x;
    int b = row >> 10;
    float4 xv = *(const float4*)(x + (size_t)row * DD + threadIdx.x * 4);
    float mu, rstd;
    row_stats(xv, mu, rstd, red);
    int d = threadIdx.x * 4;
    float4 g  = *(const float4*)(ln_g + d);
    float4 lb = *(const float4*)(ln_b + d);
    float4 ga = *(const float4*)(g_gamma + b * DD + d);
    float4 be = *(const float4*)(g_beta  + b * DD + d);
    float yx = fmaf(ga.x, fmaf((xv.x - mu) * rstd, g.x, lb.x), be.x);
    float yy = fmaf(ga.y, fmaf((xv.y - mu) * rstd, g.y, lb.y), be.y);
    float yz = fmaf(ga.z, fmaf((xv.z - mu) * rstd, g.z, lb.z), be.z);
    float yw = fmaf(ga.w, fmaf((xv.w - mu) * rstd, g.w, lb.w), be.w);
    *(uint2*)(g_hb + (size_t)row * DD + d) =
        make_uint2(pbf2(yx, yy), pbf2(yz, yw));
}

__global__ void __launch_bounds__(256) sln2_kernel(
    const float* __restrict__ ln_g, const float* __restrict__ ln_b,
    float* __restrict__ out)
{
    __shared__ float red[16];
    int row = blockIdx.x;
    int b = row >> 10;
    float4 xv = *(const float4*)(g_h1 + (size_t)row * DD + threadIdx.x * 4);
    float mu, rstd;
    row_stats(xv, mu, rstd, red);
    int d = threadIdx.x * 4;
    float4 g  = *(const float4*)(ln_g + d);
    float4 lb = *(const float4*)(ln_b + d);
    float4 ga = *(const float4*)(g_gamma + b * DD + d);
    float4 be = *(const float4*)(g_beta  + b * DD + d);
    float4 y;
    y.x = fmaf(ga.x, fmaf((xv.x - mu) * rstd, g.x, lb.x), be.x) + xv.x;
    y.y = fmaf(ga.y, fmaf((xv.y - mu) * rstd, g.y, lb.y), be.y) + xv.y;
    y.z = fmaf(ga.z, fmaf((xv.z - mu) * rstd, g.z, lb.z), be.z) + xv.z;
    y.w = fmaf(ga.w, fmaf((xv.w - mu) * rstd, g.w, lb.w), be.w) + xv.w;
    *(float4*)&out[(size_t)row * DD + d] = y;
}

// =====================================================================
extern "C" void kernel_launch(void* const* d_in, const int* in_sizes, int n_in,
                              void* d_out, int out_size)
{
    (void)in_sizes; (void)n_in; (void)out_size;
    const float* hidden = (const float*)d_in[0];
    const float* w      = (const float*)d_in[1];
    const float* ln_g   = (const float*)d_in[2];
    const float* ln_b   = (const float*)d_in[3];
    const float* Wg     = (const float*)d_in[4];
    const float* bg     = (const float*)d_in[5];
    const float* Wb     = (const float*)d_in[6];
    const float* bb     = (const float*)d_in[7];
    const float* Wqkv   = (const float*)d_in[8];
    const float* bqkv   = (const float*)d_in[9];
    const float* Wp     = (const float*)d_in[10];
    const float* bp     = (const float*)d_in[11];
    float* out = (float*)d_out;

    cudaFuncSetAttribute(mm_bf<1>, cudaFuncAttributeMaxDynamicSharedMemorySize, MM_DSMEM);
    cudaFuncSetAttribute(mm_bf<0>, cudaFuncAttributeMaxDynamicSharedMemorySize, MM_DSMEM);

    convert_wqkv<<<QKVN * DD / 1024, 256>>>(Wqkv);
    convert_wp<<<DD * DD / 1024, 256>>>(Wp);
    gammabeta_kernel<<<512, 256>>>(w, Wg, bg, Wb, bb);
    sln1_kernel<<<ROWS, 256>>>(hidden, ln_g, ln_b);
    mm_bf<1><<<dim3(QKVN / 128, ROWS / 128), 256, MM_DSMEM>>>(bqkv, hidden);
    attn_bf<<<dim3(NN / 128, BB * HH), 256>>>();
    mm_bf<0><<<dim3(DD / 128, ROWS / 128), 256, MM_DSMEM>>>(bp, hidden);
    sln2_kernel<<<ROWS, 256>>>(ln_g, ln_b, out);
}

// round 7
// speedup vs baseline: 4.7630x; 1.0963x over previous
#include <cuda_runtime.h>
#include <cstdint>

// ---------------- problem dims ----------------
#define BB 4
#define NN 1024
#define DD 1024
#define HH 16
#define HD 64
#define ROWS (BB*NN)      // 4096
#define QKVN (3*DD)       // 3072

// ---------------- scratch ----------------
__device__ float    g_gamma[BB*DD];
__device__ float    g_beta[BB*DD];
__device__ uint16_t g_hb[ROWS*DD];          // SLN(hidden), bf16
__device__ uint16_t g_wqkvb[QKVN*DD];       // Wqkv bf16, pre-permuted rows
__device__ uint16_t g_wpb[DD*DD];           // Wp bf16
__device__ uint16_t g_qb[BB*HH*NN*HD];      // [bh][n][d]
__device__ uint16_t g_kb[BB*HH*NN*HD];      // [bh][n][d]
__device__ uint16_t g_vtb[BB*HH*HD*NN];     // [bh][d][n]  (transposed V)
__device__ uint16_t g_aob[ROWS*DD];         // attention out bf16
__device__ float    g_h1[ROWS*DD];

// ================= helpers =================
__device__ __forceinline__ uint32_t smem_u32(const void* p) {
    uint32_t a;
    asm("{ .reg .u64 t; cvta.to.shared.u64 t, %1; cvt.u32.u64 %0, t; }"
        : "=r"(a) : "l"(p));
    return a;
}
__device__ __forceinline__ void cp16(uint32_t dst, const void* src) {
    asm volatile("cp.async.cg.shared.global [%0], [%1], 16;"
                 :: "r"(dst), "l"(src) : "memory");
}
__device__ __forceinline__ void cp_commit() {
    asm volatile("cp.async.commit_group;" ::: "memory");
}
template<int N>
__device__ __forceinline__ void cp_wait() {
    asm volatile("cp.async.wait_group %0;" :: "n"(N) : "memory");
}
// pack two f32 -> bf16x2 (lo = first arg at lower address)
__device__ __forceinline__ uint32_t pbf2(float lo, float hi) {
    uint32_t r;
    asm("cvt.rn.bf16x2.f32 %0, %1, %2;" : "=r"(r) : "f"(hi), "f"(lo));
    return r;
}
__device__ __forceinline__ uint16_t bf1(float x) {
    uint16_t r; asm("cvt.rn.bf16.f32 %0, %1;" : "=h"(r) : "f"(x)); return r;
}
__device__ __forceinline__ void mma_bf16(float* d, const uint32_t* a,
                                         uint32_t b0, uint32_t b1) {
    asm volatile("mma.sync.aligned.m16n8k16.row.col.f32.bf16.bf16.f32 "
        "{%0,%1,%2,%3}, {%4,%5,%6,%7}, {%8,%9}, {%0,%1,%2,%3};"
        : "+f"(d[0]), "+f"(d[1]), "+f"(d[2]), "+f"(d[3])
        : "r"(a[0]), "r"(a[1]), "r"(a[2]), "r"(a[3]), "r"(b0), "r"(b1));
}
__device__ __forceinline__ void ldsm4(uint32_t& r0, uint32_t& r1,
                                      uint32_t& r2, uint32_t& r3, uint32_t a) {
    asm volatile("ldmatrix.sync.aligned.m8n8.x4.shared.b16 {%0,%1,%2,%3}, [%4];"
        : "=r"(r0), "=r"(r1), "=r"(r2), "=r"(r3) : "r"(a));
}

// ================= weight conversion (fused, per-launch) =======
__global__ void __launch_bounds__(256) convert_w(
    const float* __restrict__ Wqkv, const float* __restrict__ Wp)
{
    int e = (blockIdx.x * 256 + threadIdx.x) * 4;
    if (e < QKVN * DD) {
        int j = e >> 10, k = e & 1023;
        int pj = ((j & 1023) >> 6) * 192 + (j & 63) * 3 + (j >> 10);
        float4 v = *(const float4*)(Wqkv + (size_t)pj * DD + k);
        *(uint2*)(g_wqkvb + e) = make_uint2(pbf2(v.x, v.y), pbf2(v.z, v.w));
    } else {
        int e2 = e - QKVN * DD;
        float4 v = *(const float4*)(Wp + e2);
        *(uint2*)(g_wpb + e2) = make_uint2(pbf2(v.x, v.y), pbf2(v.z, v.w));
    }
}

// =====================================================================
// bf16 GEMM via mma.m16n8k16 + 3-stage cp.async ring + ldmatrix frags.
// C tile 128x128, K=1024 in 32 stages of 32. smem row 40 bf16 (80 B);
// ldmatrix 8-row groups at stride 80B hit distinct bank quads.
// =====================================================================
#define MSTB 40
#define MM_STAGE (128 * MSTB)                 // uint16 elems per matrix stage
#define MM_SBYTES (MM_STAGE * 2)              // 10240 bytes
#define MM_DSMEM (6 * MM_SBYTES)              // 61440 bytes

template<int QKV>
__global__ void __launch_bounds__(256, 2) mm_bf(
    const float* __restrict__ bias, const float* __restrict__ resid)
{
    extern __shared__ uint16_t smb[];
    uint16_t* Abuf = smb;                     // [3][128*40]
    uint16_t* Bbuf = smb + 3 * MM_STAGE;

    const int tid = threadIdx.x, lane = tid & 31, wid = tid >> 5;
    const int bm = blockIdx.y * 128, bn = blockIdx.x * 128;
    const uint16_t* Asrc = QKV ? g_hb : g_aob;
    const uint16_t* Bsrc = QKV ? g_wqkvb : g_wpb;

    // loader: row r = tid>>1, half hh = tid&1 (32B each)
    const int r = tid >> 1, hh = tid & 1;
    const uint16_t* aptr = Asrc + (size_t)(bm + r) * DD + hh * 16;
    const uint16_t* bptr = Bsrc + (size_t)(bn + r) * DD + hh * 16;
    uint32_t sA[3], sB[3];
    #pragma unroll
    for (int s = 0; s < 3; s++) {
        sA[s] = smem_u32(Abuf + s * MM_STAGE + r * MSTB + hh * 16);
        sB[s] = smem_u32(Bbuf + s * MM_STAGE + r * MSTB + hh * 16);
    }

    const int wm = (wid & 1) * 64, wn = (wid >> 1) * 32;
    const int g = lane >> 2, cc = lane & 3, c2 = cc * 2;

    // ldmatrix lane offsets (bytes)
    const uint32_t abase0 = smem_u32(Abuf);
    const uint32_t bbase0 = smem_u32(Bbuf);
    const uint32_t laneA = ((lane >> 3) & 1) * 640 + (lane & 7) * 80 +
                           ((lane >> 4) & 1) * 16 + wm * 80;
    const uint32_t laneB = ((lane >> 4) & 1) * 640 + (lane & 7) * 80 +
                           ((lane >> 3) & 1) * 16 + wn * 80;

    float acc[4][4][4];
    #pragma unroll
    for (int mt = 0; mt < 4; mt++)
        #pragma unroll
        for (int nt = 0; nt < 4; nt++)
            #pragma unroll
            for (int e = 0; e < 4; e++) acc[mt][nt][e] = 0.f;

    // prologue: stages 0,1
    #pragma unroll
    for (int s = 0; s < 2; s++) {
        cp16(sA[s], aptr + s * 32);  cp16(sA[s] + 16, aptr + s * 32 + 8);
        cp16(sB[s], bptr + s * 32);  cp16(sB[s] + 16, bptr + s * 32 + 8);
        cp_commit();
    }

    for (int t = 0; t < 32; t++) {
        const int buf = t % 3;
        if (t < 30) cp_wait<1>(); else cp_wait<0>();
        __syncthreads();
        if (t + 2 < 32) {
            const int s = (t + 2) % 3;
            const uint16_t* ap = aptr + (t + 2) * 32;
            const uint16_t* bp = bptr + (t + 2) * 32;
            cp16(sA[s], ap);  cp16(sA[s] + 16, ap + 8);
            cp16(sB[s], bp);  cp16(sB[s] + 16, bp + 8);
            cp_commit();
        }
        const uint32_t aAddr = abase0 + buf * MM_SBYTES + laneA;
        const uint32_t bAddr = bbase0 + buf * MM_SBYTES + laneB;
        #pragma unroll
        for (int kc = 0; kc < 2; kc++) {
            uint32_t af[4][4], bfr[4][2];
            #pragma unroll
            for (int mt = 0; mt < 4; mt++)
                ldsm4(af[mt][0], af[mt][1], af[mt][2], af[mt][3],
                      aAddr + mt * 1280 + kc * 32);
            #pragma unroll
            for (int np = 0; np < 2; np++)
                ldsm4(bfr[2*np][0], bfr[2*np][1], bfr[2*np+1][0], bfr[2*np+1][1],
                      bAddr + np * 1280 + kc * 32);
            #pragma unroll
            for (int mt = 0; mt < 4; mt++)
                #pragma unroll
                for (int nt = 0; nt < 4; nt++)
                    mma_bf16(acc[mt][nt], af[mt], bfr[nt][0], bfr[nt][1]);
        }
    }

    // ---- epilogue ----
    #pragma unroll
    for (int mt = 0; mt < 4; mt++) {
        #pragma unroll
        for (int nt = 0; nt < 4; nt++) {
            int R0 = bm + wm + mt * 16 + g;
            int C  = bn + wn + nt * 8 + c2;
            float v00 = acc[mt][nt][0], v01 = acc[mt][nt][1];
            float v10 = acc[mt][nt][2], v11 = acc[mt][nt][3];
            if (QKV) {
                int arr = C >> 10, rem = C & 1023;
                int head = rem >> 6, dd = rem & 63;
                float bx = bias[head * 192 + dd * 3 + arr];
                float by = bias[head * 192 + (dd + 1) * 3 + arr];
                int b0 = R0 >> 10, n0 = R0 & 1023;
                if (arr < 2) {
                    uint16_t* dst = arr ? g_kb : g_qb;
                    size_t base = ((size_t)(b0 * HH + head)) * NN;
                    *(uint32_t*)(dst + (base + n0) * HD + dd) =
                        pbf2(v00 + bx, v01 + by);
                    *(uint32_t*)(dst + (base + n0 + 8) * HD + dd) =
                        pbf2(v10 + bx, v11 + by);
                } else {
                    size_t vb = ((size_t)(b0 * HH + head)) * HD;
                    g_vtb[(vb + dd)     * NN + n0]     = bf1(v00 + bx);
                    g_vtb[(vb + dd + 1) * NN + n0]     = bf1(v01 + by);
                    g_vtb[(vb + dd)     * NN + n0 + 8] = bf1(v10 + bx);
                    g_vtb[(vb + dd + 1) * NN + n0 + 8] = bf1(v11 + by);
                }
            } else {
                float2 bb = *(const float2*)(bias + C);
                float2 h0 = *(const float2*)(resid + (size_t)R0 * DD + C);
                float2 h1 = *(const float2*)(resid + (size_t)(R0 + 8) * DD + C);
                *(float2*)&g_h1[(size_t)R0 * DD + C] =
                    make_float2(v00 + bb.x + h0.x, v01 + bb.y + h0.y);
                *(float2*)&g_h1[(size_t)(R0 + 8) * DD + C] =
                    make_float2(v10 + bb.x + h1.x, v11 + bb.y + h1.y);
            }
        }
    }
}

// =====================================================================
// Flash attention, bf16 m16n8k16 + ldmatrix frags.
// Ks[buf][key][dim] stride 72 bf16 (144 B rows; ldmatrix conflict-free)
// Vt[buf][dim][key] stride 72
// =====================================================================
__global__ void __launch_bounds__(256, 2) attn_bf()
{
    __shared__ uint16_t Ks[2][64 * 72];
    __shared__ uint16_t Vt[2][64 * 72];

    const int tid = threadIdx.x, lane = tid & 31, w = tid >> 5;
    const int g = lane >> 2, cc = lane & 3, c2 = cc * 2;
    const int bh = blockIdx.y, qt = blockIdx.x;

    const uint16_t* Kg = g_kb + (size_t)bh * NN * HD;
    const uint16_t* Vg = g_vtb + (size_t)bh * HD * NN;

    // loader: 4 threads/row, 32B each
    const int lrow = tid >> 2;
    const int lcq  = (tid & 3) * 16;
    const uint16_t* kpb = Kg + lrow * HD + lcq;
    const uint16_t* vpb = Vg + (size_t)lrow * NN + lcq;
    uint32_t skb[2], svb[2];
    skb[0] = smem_u32(&Ks[0][lrow * 72 + lcq]);
    skb[1] = smem_u32(&Ks[1][lrow * 72 + lcq]);
    svb[0] = smem_u32(&Vt[0][lrow * 72 + lcq]);
    svb[1] = smem_u32(&Vt[1][lrow * 72 + lcq]);

    // ldmatrix lane offset (bytes): rows stride 144
    const uint32_t lmoff = ((lane >> 4) & 1) * 1152 + (lane & 7) * 144 +
                           ((lane >> 3) & 1) * 16;
    const uint32_t kfb[2] = { smem_u32(Ks[0]) + lmoff, smem_u32(Ks[1]) + lmoff };
    const uint32_t vfb[2] = { smem_u32(Vt[0]) + lmoff, smem_u32(Vt[1]) + lmoff };

    // prologue: tile 0 -> buf 0
    cp16(skb[0], kpb);  cp16(skb[0] + 16, kpb + 8);
    cp16(svb[0], vpb);  cp16(svb[0] + 16, vpb + 8);
    cp_commit();

    // Q fragments (bf16), resident
    const uint32_t* Qg32 =
        (const uint32_t*)(g_qb + ((size_t)bh * NN + qt * 128 + w * 16) * HD);
    uint32_t qf[4][4];
    #pragma unroll
    for (int kc = 0; kc < 4; kc++) {
        qf[kc][0] = Qg32[g * 32 + kc * 8 + cc];
        qf[kc][1] = Qg32[(g + 8) * 32 + kc * 8 + cc];
        qf[kc][2] = Qg32[g * 32 + kc * 8 + cc + 4];
        qf[kc][3] = Qg32[(g + 8) * 32 + kc * 8 + cc + 4];
    }

    float o[8][4];
    #pragma unroll
    for (int nt = 0; nt < 8; nt++)
        #pragma unroll
        for (int e = 0; e < 4; e++) o[nt][e] = 0.f;
    float m0 = -1e30f, m1 = -1e30f, l0 = 0.f, l1 = 0.f;

    for (int t = 0; t < 16; t++) {
        const int buf = t & 1;
        cp_wait<0>();
        __syncthreads();
        if (t < 15) {
            const uint16_t* kp = kpb + (size_t)(t + 1) * 64 * HD;
            const uint16_t* vp = vpb + (t + 1) * 64;
            cp16(skb[buf ^ 1], kp);  cp16(skb[buf ^ 1] + 16, kp + 8);
            cp16(svb[buf ^ 1], vp);  cp16(svb[buf ^ 1] + 16, vp + 8);
            cp_commit();
        }

        // ---- S = Q K^T ---- (ldmatrix: one x4 per (nt-pair, kc))
        float s[8][4];
        #pragma unroll
        for (int nt = 0; nt < 8; nt++)
            s[nt][0] = s[nt][1] = s[nt][2] = s[nt][3] = 0.f;
        #pragma unroll
        for (int np = 0; np < 4; np++) {
            #pragma unroll
            for (int kc = 0; kc < 4; kc++) {
                uint32_t t0, t1, t2, t3;
                ldsm4(t0, t1, t2, t3, kfb[buf] + np * 2304 + kc * 32);
                mma_bf16(s[2*np],     qf[kc], t0, t1);
                mma_bf16(s[2*np + 1], qf[kc], t2, t3);
            }
        }

        // ---- online softmax ----
        float rmax0 = -1e30f, rmax1 = -1e30f;
        #pragma unroll
        for (int nt = 0; nt < 8; nt++) {
            rmax0 = fmaxf(rmax0, fmaxf(s[nt][0], s[nt][1]));
            rmax1 = fmaxf(rmax1, fmaxf(s[nt][2], s[nt][3]));
        }
        rmax0 = fmaxf(rmax0, __shfl_xor_sync(0xffffffffu, rmax0, 1));
        rmax0 = fmaxf(rmax0, __shfl_xor_sync(0xffffffffu, rmax0, 2));
        rmax1 = fmaxf(rmax1, __shfl_xor_sync(0xffffffffu, rmax1, 1));
        rmax1 = fmaxf(rmax1, __shfl_xor_sync(0xffffffffu, rmax1, 2));
        float mn0 = fmaxf(m0, rmax0), mn1 = fmaxf(m1, rmax1);
        float sc0 = __expf(m0 - mn0), sc1 = __expf(m1 - mn1);
        m0 = mn0; m1 = mn1;
        float rs0 = 0.f, rs1 = 0.f;
        #pragma unroll
        for (int nt = 0; nt < 8; nt++) {
            s[nt][0] = __expf(s[nt][0] - mn0); rs0 += s[nt][0];
            s[nt][1] = __expf(s[nt][1] - mn0); rs0 += s[nt][1];
            s[nt][2] = __expf(s[nt][2] - mn1); rs1 += s[nt][2];
            s[nt][3] = __expf(s[nt][3] - mn1); rs1 += s[nt][3];
        }
        rs0 += __shfl_xor_sync(0xffffffffu, rs0, 1);
        rs0 += __shfl_xor_sync(0xffffffffu, rs0, 2);
        rs1 += __shfl_xor_sync(0xffffffffu, rs1, 1);
        rs1 += __shfl_xor_sync(0xffffffffu, rs1, 2);
        l0 = l0 * sc0 + rs0;
        l1 = l1 * sc1 + rs1;
        #pragma unroll
        for (int nt = 0; nt < 8; nt++) {
            o[nt][0] *= sc0; o[nt][1] *= sc0;
            o[nt][2] *= sc1; o[nt][3] *= sc1;
        }

        // ---- P: C-frag -> bf16 A-frag (register-only) ----
        uint32_t pa[4][4];
        #pragma unroll
        for (int kc = 0; kc < 4; kc++) {
            pa[kc][0] = pbf2(s[2 * kc][0],     s[2 * kc][1]);
            pa[kc][1] = pbf2(s[2 * kc][2],     s[2 * kc][3]);
            pa[kc][2] = pbf2(s[2 * kc + 1][0], s[2 * kc + 1][1]);
            pa[kc][3] = pbf2(s[2 * kc + 1][2], s[2 * kc + 1][3]);
        }

        // ---- O += P V ----
        #pragma unroll
        for (int np = 0; np < 4; np++) {
            #pragma unroll
            for (int kc = 0; kc < 4; kc++) {
                uint32_t t0, t1, t2, t3;
                ldsm4(t0, t1, t2, t3, vfb[buf] + np * 2304 + kc * 32);
                mma_bf16(o[2*np],     pa[kc], t0, t1);
                mma_bf16(o[2*np + 1], pa[kc], t2, t3);
            }
        }
    }

    // ---- output: bf16(o / (l * 32)) -> g_aob ----
    const int b = bh >> 4, head = bh & 15;
    const int row0 = qt * 128 + w * 16 + g;
    float inv0 = 1.0f / (l0 * 32.0f);
    float inv1 = 1.0f / (l1 * 32.0f);
    uint32_t* d0 = (uint32_t*)(g_aob + ((size_t)b * NN + row0) * DD + head * HD);
    uint32_t* d1 = (uint32_t*)(g_aob + ((size_t)b * NN + row0 + 8) * DD + head * HD);
    #pragma unroll
    for (int nt = 0; nt < 8; nt++) {
        d0[nt * 4 + cc] = pbf2(o[nt][0] * inv0, o[nt][1] * inv0);
        d1[nt * 4 + cc] = pbf2(o[nt][2] * inv1, o[nt][3] * inv1);
    }
}

// ================= gamma/beta GEMV (float4) =================
__global__ void __launch_bounds__(256) gammabeta_kernel(
    const float* __restrict__ w,  const float* __restrict__ Wg,
    const float* __restrict__ bg, const float* __restrict__ Wb,
    const float* __restrict__ bb)
{
    int lane = threadIdx.x & 31;
    int warp = threadIdx.x >> 5;
    int gid  = blockIdx.x * 8 + warp;
    int b = gid >> 10, d = gid & 1023;
    const float* wrow = w  + b * DD;
    const float* wg   = Wg + (size_t)d * DD;
    const float* wb   = Wb + (size_t)d * DD;
    float sg = 0.f, sb = 0.f;
    #pragma unroll
    for (int it = 0; it < 8; it++) {
        int k = it * 128 + lane * 4;
        float4 wk = *(const float4*)(wrow + k);
        float4 a  = *(const float4*)(wg + k);
        float4 c  = *(const float4*)(wb + k);
        sg = fmaf(wk.x, a.x, fmaf(wk.y, a.y, fmaf(wk.z, a.z, fmaf(wk.w, a.w, sg))));
        sb = fmaf(wk.x, c.x, fmaf(wk.y, c.y, fmaf(wk.z, c.z, fmaf(wk.w, c.w, sb))));
    }
    #pragma unroll
    for (int o = 16; o; o >>= 1) {
        sg += __shfl_xor_sync(0xffffffffu, sg, o);
        sb += __shfl_xor_sync(0xffffffffu, sb, o);
    }
    if (!lane) {
        g_gamma[gid] = sg + bg[d];
        g_beta[gid]  = sb + bb[d];
    }
}

// ================= SLN kernels =================
__device__ __forceinline__ void row_stats(float4 xv, float& mu, float& rstd,
                                          float* red)
{
    float s = xv.x + xv.y + xv.z + xv.w;
    float q = xv.x*xv.x + xv.y*xv.y + xv.z*xv.z + xv.w*xv.w;
    #pragma unroll
    for (int o = 16; o; o >>= 1) {
        s += __shfl_xor_sync(0xffffffffu, s, o);
        q += __shfl_xor_sync(0xffffffffu, q, o);
    }
    int warp = threadIdx.x >> 5, lane = threadIdx.x & 31;
    if (!lane) { red[warp] = s; red[8 + warp] = q; }
    __syncthreads();
    float ss = 0.f, qq = 0.f;
    #pragma unroll
    for (int i = 0; i < 8; i++) { ss += red[i]; qq += red[8 + i]; }
    mu = ss * (1.0f / DD);
    float var = qq * (1.0f / DD) - mu * mu;
    rstd = rsqrtf(var + 1e-5f);
}

__global__ void __launch_bounds__(256) sln1_kernel(
    const float* __restrict__ x, const float* __restrict__ ln_g,
    const float* __restrict__ ln_b)
{
    __shared__ float red[16];
    int row = blockIdx.x;
    int b = row >> 10;
    float4 xv = *(const float4*)(x + (size_t)row * DD + threadIdx.x * 4);
    float mu, rstd;
    row_stats(xv, mu, rstd, red);
    int d = threadIdx.x * 4;
    float4 g  = *(const float4*)(ln_g + d);
    float4 lb = *(const float4*)(ln_b + d);
    float4 ga = *(const float4*)(g_gamma + b * DD + d);
    float4 be = *(const float4*)(g_beta  + b * DD + d);
    float yx = fmaf(ga.x, fmaf((xv.x - mu) * rstd, g.x, lb.x), be.x);
    float yy = fmaf(ga.y, fmaf((xv.y - mu) * rstd, g.y, lb.y), be.y);
    float yz = fmaf(ga.z, fmaf((xv.z - mu) * rstd, g.z, lb.z), be.z);
    float yw = fmaf(ga.w, fmaf((xv.w - mu) * rstd, g.w, lb.w), be.w);
    *(uint2*)(g_hb + (size_t)row * DD + d) =
        make_uint2(pbf2(yx, yy), pbf2(yz, yw));
}

__global__ void __launch_bounds__(256) sln2_kernel(
    const float* __restrict__ ln_g, const float* __restrict__ ln_b,
    float* __restrict__ out)
{
    __shared__ float red[16];
    int row = blockIdx.x;
    int b = row >> 10;
    float4 xv = *(const float4*)(g_h1 + (size_t)row * DD + threadIdx.x * 4);
    float mu, rstd;
    row_stats(xv, mu, rstd, red);
    int d = threadIdx.x * 4;
    float4 g  = *(const float4*)(ln_g + d);
    float4 lb = *(const float4*)(ln_b + d);
    float4 ga = *(const float4*)(g_gamma + b * DD + d);
    float4 be = *(const float4*)(g_beta  + b * DD + d);
    float4 y;
    y.x = fmaf(ga.x, fmaf((xv.x - mu) * rstd, g.x, lb.x), be.x) + xv.x;
    y.y = fmaf(ga.y, fmaf((xv.y - mu) * rstd, g.y, lb.y), be.y) + xv.y;
    y.z = fmaf(ga.z, fmaf((xv.z - mu) * rstd, g.z, lb.z), be.z) + xv.z;
    y.w = fmaf(ga.w, fmaf((xv.w - mu) * rstd, g.w, lb.w), be.w) + xv.w;
    *(float4*)&out[(size_t)row * DD + d] = y;
}

// =====================================================================
extern "C" void kernel_launch(void* const* d_in, const int* in_sizes, int n_in,
                              void* d_out, int out_size)
{
    (void)in_sizes; (void)n_in; (void)out_size;
    const float* hidden = (const float*)d_in[0];
    const float* w      = (const float*)d_in[1];
    const float* ln_g   = (const float*)d_in[2];
    const float* ln_b   = (const float*)d_in[3];
    const float* Wg     = (const float*)d_in[4];
    const float* bg     = (const float*)d_in[5];
    const float* Wb     = (const float*)d_in[6];
    const float* bb     = (const float*)d_in[7];
    const float* Wqkv   = (const float*)d_in[8];
    const float* bqkv   = (const float*)d_in[9];
    const float* Wp     = (const float*)d_in[10];
    const float* bp     = (const float*)d_in[11];
    float* out = (float*)d_out;

    cudaFuncSetAttribute(mm_bf<1>, cudaFuncAttributeMaxDynamicSharedMemorySize, MM_DSMEM);
    cudaFuncSetAttribute(mm_bf<0>, cudaFuncAttributeMaxDynamicSharedMemorySize, MM_DSMEM);

    convert_w<<<(QKVN + DD) * DD / 1024, 256>>>(Wqkv, Wp);
    gammabeta_kernel<<<512, 256>>>(w, Wg, bg, Wb, bb);
    sln1_kernel<<<ROWS, 256>>>(hidden, ln_g, ln_b);
    mm_bf<1><<<dim3(QKVN / 128, ROWS / 128), 256, MM_DSMEM>>>(bqkv, hidden);
    attn_bf<<<dim3(NN / 128, BB * HH), 256>>>();
    mm_bf<0><<<dim3(DD / 128, ROWS / 128), 256, MM_DSMEM>>>(bp, hidden);
    sln2_kernel<<<ROWS, 256>>>(ln_g, ln_b, out);
}

// round 8
// speedup vs baseline: 5.2685x; 1.1061x over previous
#include <cuda_runtime.h>
#include <cstdint>

// ---------------- problem dims ----------------
#define BB 4
#define NN 1024
#define DD 1024
#define HH 16
#define HD 64
#define ROWS (BB*NN)      // 4096
#define QKVN (3*DD)       // 3072

// ---------------- scratch ----------------
__device__ float    g_gamma[BB*DD];
__device__ float    g_beta[BB*DD];
__device__ uint16_t g_hb[ROWS*DD];          // SLN(hidden), bf16
__device__ uint16_t g_wqkvb[QKVN*DD];       // Wqkv bf16, pre-permuted rows
__device__ uint16_t g_wpb[DD*DD];           // Wp bf16
__device__ uint16_t g_qb[BB*HH*NN*HD];      // [bh][n][d]
__device__ uint16_t g_kb[BB*HH*NN*HD];      // [bh][n][d]
__device__ uint16_t g_vtb[BB*HH*HD*NN];     // [bh][d][n]  (transposed V)
__device__ uint16_t g_aob[ROWS*DD];         // attention out bf16
__device__ float    g_h1[ROWS*DD];

// ================= helpers =================
__device__ __forceinline__ uint32_t smem_u32(const void* p) {
    uint32_t a;
    asm("{ .reg .u64 t; cvta.to.shared.u64 t, %1; cvt.u32.u64 %0, t; }"
        : "=r"(a) : "l"(p));
    return a;
}
__device__ __forceinline__ void cp16(uint32_t dst, const void* src) {
    asm volatile("cp.async.cg.shared.global [%0], [%1], 16;"
                 :: "r"(dst), "l"(src) : "memory");
}
__device__ __forceinline__ void cp_commit() {
    asm volatile("cp.async.commit_group;" ::: "memory");
}
template<int N>
__device__ __forceinline__ void cp_wait() {
    asm volatile("cp.async.wait_group %0;" :: "n"(N) : "memory");
}
// pack two f32 -> bf16x2 (lo = first arg at lower address)
__device__ __forceinline__ uint32_t pbf2(float lo, float hi) {
    uint32_t r;
    asm("cvt.rn.bf16x2.f32 %0, %1, %2;" : "=r"(r) : "f"(hi), "f"(lo));
    return r;
}
__device__ __forceinline__ uint16_t bf1(float x) {
    uint16_t r; asm("cvt.rn.bf16.f32 %0, %1;" : "=h"(r) : "f"(x)); return r;
}
__device__ __forceinline__ void mma_bf16(float* d, const uint32_t* a,
                                         uint32_t b0, uint32_t b1) {
    asm volatile("mma.sync.aligned.m16n8k16.row.col.f32.bf16.bf16.f32 "
        "{%0,%1,%2,%3}, {%4,%5,%6,%7}, {%8,%9}, {%0,%1,%2,%3};"
        : "+f"(d[0]), "+f"(d[1]), "+f"(d[2]), "+f"(d[3])
        : "r"(a[0]), "r"(a[1]), "r"(a[2]), "r"(a[3]), "r"(b0), "r"(b1));
}
__device__ __forceinline__ void ldsm4(uint32_t& r0, uint32_t& r1,
                                      uint32_t& r2, uint32_t& r3, uint32_t a) {
    asm volatile("ldmatrix.sync.aligned.m8n8.x4.shared.b16 {%0,%1,%2,%3}, [%4];"
        : "=r"(r0), "=r"(r1), "=r"(r2), "=r"(r3) : "r"(a));
}

// ================= weight conversion (fused, per-launch) =======
__global__ void __launch_bounds__(256) convert_w(
    const float* __restrict__ Wqkv, const float* __restrict__ Wp)
{
    int e = (blockIdx.x * 256 + threadIdx.x) * 4;
    if (e < QKVN * DD) {
        int j = e >> 10, k = e & 1023;
        int pj = ((j & 1023) >> 6) * 192 + (j & 63) * 3 + (j >> 10);
        float4 v = *(const float4*)(Wqkv + (size_t)pj * DD + k);
        *(uint2*)(g_wqkvb + e) = make_uint2(pbf2(v.x, v.y), pbf2(v.z, v.w));
    } else {
        int e2 = e - QKVN * DD;
        float4 v = *(const float4*)(Wp + e2);
        *(uint2*)(g_wpb + e2) = make_uint2(pbf2(v.x, v.y), pbf2(v.z, v.w));
    }
}

// =====================================================================
// bf16 GEMM: mma.m16n8k16, 4-stage cp.async ring (wait_group<2> -> up to
// 3 loads in flight), ldmatrix frags. C tile 128x128, 32 K-stages of 32.
// =====================================================================
#define MSTB 40
#define MM_STAGE (128 * MSTB)                 // uint16 elems per matrix stage
#define MM_SBYTES (MM_STAGE * 2)              // 10240 bytes
#define MM_NST 4
#define MM_DSMEM (2 * MM_NST * MM_SBYTES)     // 81920 bytes

template<int QKV>
__global__ void __launch_bounds__(256, 2) mm_bf(
    const float* __restrict__ bias, const float* __restrict__ resid)
{
    extern __shared__ uint16_t smb[];
    uint16_t* Abuf = smb;                     // [4][128*40]
    uint16_t* Bbuf = smb + MM_NST * MM_STAGE;

    const int tid = threadIdx.x, lane = tid & 31, wid = tid >> 5;
    const int bm = blockIdx.y * 128, bn = blockIdx.x * 128;
    const uint16_t* Asrc = QKV ? g_hb : g_aob;
    const uint16_t* Bsrc = QKV ? g_wqkvb : g_wpb;

    // loader: row r = tid>>1, half hh = tid&1 (32B each)
    const int r = tid >> 1, hh = tid & 1;
    const uint16_t* aptr = Asrc + (size_t)(bm + r) * DD + hh * 16;
    const uint16_t* bptr = Bsrc + (size_t)(bn + r) * DD + hh * 16;
    uint32_t sA[MM_NST], sB[MM_NST];
    #pragma unroll
    for (int s = 0; s < MM_NST; s++) {
        sA[s] = smem_u32(Abuf + s * MM_STAGE + r * MSTB + hh * 16);
        sB[s] = smem_u32(Bbuf + s * MM_STAGE + r * MSTB + hh * 16);
    }

    const int wm = (wid & 1) * 64, wn = (wid >> 1) * 32;
    const int g = lane >> 2, cc = lane & 3, c2 = cc * 2;

    // ldmatrix lane offsets (bytes)
    const uint32_t abase0 = smem_u32(Abuf);
    const uint32_t bbase0 = smem_u32(Bbuf);
    const uint32_t laneA = ((lane >> 3) & 1) * 640 + (lane & 7) * 80 +
                           ((lane >> 4) & 1) * 16 + wm * 80;
    const uint32_t laneB = ((lane >> 4) & 1) * 640 + (lane & 7) * 80 +
                           ((lane >> 3) & 1) * 16 + wn * 80;

    float acc[4][4][4];
    #pragma unroll
    for (int mt = 0; mt < 4; mt++)
        #pragma unroll
        for (int nt = 0; nt < 4; nt++)
            #pragma unroll
            for (int e = 0; e < 4; e++) acc[mt][nt][e] = 0.f;

    // prologue: stages 0,1,2
    #pragma unroll
    for (int s = 0; s < 3; s++) {
        cp16(sA[s], aptr + s * 32);  cp16(sA[s] + 16, aptr + s * 32 + 8);
        cp16(sB[s], bptr + s * 32);  cp16(sB[s] + 16, bptr + s * 32 + 8);
        cp_commit();
    }

    for (int t = 0; t < 32; t++) {
        const int buf = t & 3;
        if (t < 30) cp_wait<2>(); else cp_wait<0>();
        __syncthreads();
        if (t + 3 < 32) {
            const int s = (t + 3) & 3;
            const uint16_t* ap = aptr + (t + 3) * 32;
            const uint16_t* bp = bptr + (t + 3) * 32;
            cp16(sA[s], ap);  cp16(sA[s] + 16, ap + 8);
            cp16(sB[s], bp);  cp16(sB[s] + 16, bp + 8);
            cp_commit();
        }
        const uint32_t aAddr = abase0 + buf * MM_SBYTES + laneA;
        const uint32_t bAddr = bbase0 + buf * MM_SBYTES + laneB;
        #pragma unroll
        for (int kc = 0; kc < 2; kc++) {
            uint32_t af[4][4], bfr[4][2];
            #pragma unroll
            for (int mt = 0; mt < 4; mt++)
                ldsm4(af[mt][0], af[mt][1], af[mt][2], af[mt][3],
                      aAddr + mt * 1280 + kc * 32);
            #pragma unroll
            for (int np = 0; np < 2; np++)
                ldsm4(bfr[2*np][0], bfr[2*np][1], bfr[2*np+1][0], bfr[2*np+1][1],
                      bAddr + np * 1280 + kc * 32);
            #pragma unroll
            for (int mt = 0; mt < 4; mt++)
                #pragma unroll
                for (int nt = 0; nt < 4; nt++)
                    mma_bf16(acc[mt][nt], af[mt], bfr[nt][0], bfr[nt][1]);
        }
    }

    // ---- epilogue ----
    #pragma unroll
    for (int mt = 0; mt < 4; mt++) {
        #pragma unroll
        for (int nt = 0; nt < 4; nt++) {
            int R0 = bm + wm + mt * 16 + g;
            int C  = bn + wn + nt * 8 + c2;
            float v00 = acc[mt][nt][0], v01 = acc[mt][nt][1];
            float v10 = acc[mt][nt][2], v11 = acc[mt][nt][3];
            if (QKV) {
                int arr = C >> 10, rem = C & 1023;
                int head = rem >> 6, dd = rem & 63;
                float bx = bias[head * 192 + dd * 3 + arr];
                float by = bias[head * 192 + (dd + 1) * 3 + arr];
                int b0 = R0 >> 10, n0 = R0 & 1023;
                if (arr < 2) {
                    uint16_t* dst = arr ? g_kb : g_qb;
                    size_t base = ((size_t)(b0 * HH + head)) * NN;
                    *(uint32_t*)(dst + (base + n0) * HD + dd) =
                        pbf2(v00 + bx, v01 + by);
                    *(uint32_t*)(dst + (base + n0 + 8) * HD + dd) =
                        pbf2(v10 + bx, v11 + by);
                } else {
                    size_t vb = ((size_t)(b0 * HH + head)) * HD;
                    g_vtb[(vb + dd)     * NN + n0]     = bf1(v00 + bx);
                    g_vtb[(vb + dd + 1) * NN + n0]     = bf1(v01 + by);
                    g_vtb[(vb + dd)     * NN + n0 + 8] = bf1(v10 + bx);
                    g_vtb[(vb + dd + 1) * NN + n0 + 8] = bf1(v11 + by);
                }
            } else {
                float2 bb = *(const float2*)(bias + C);
                float2 h0 = *(const float2*)(resid + (size_t)R0 * DD + C);
                float2 h1 = *(const float2*)(resid + (size_t)(R0 + 8) * DD + C);
                *(float2*)&g_h1[(size_t)R0 * DD + C] =
                    make_float2(v00 + bb.x + h0.x, v01 + bb.y + h0.y);
                *(float2*)&g_h1[(size_t)(R0 + 8) * DD + C] =
                    make_float2(v10 + bb.x + h1.x, v11 + bb.y + h1.y);
            }
        }
    }
}

// =====================================================================
// Flash attention, bf16 m16n8k16 + ldmatrix, 3-stage cp.async ring.
// Ks[s][key][dim] stride 72 bf16 ; Vt[s][dim][key] stride 72 (dynamic smem)
// =====================================================================
#define AT_STAGE (64 * 72)                    // uint16 per matrix stage
#define AT_SBYTES (AT_STAGE * 2)              // 9216 bytes
#define AT_DSMEM (6 * AT_SBYTES)              // 55296 bytes

__global__ void __launch_bounds__(256, 2) attn_bf()
{
    extern __shared__ uint16_t sma[];
    uint16_t* Ksb = sma;                      // [3][64*72]
    uint16_t* Vtb = sma + 3 * AT_STAGE;

    const int tid = threadIdx.x, lane = tid & 31, w = tid >> 5;
    const int g = lane >> 2, cc = lane & 3, c2 = cc * 2;
    const int bh = blockIdx.y, qt = blockIdx.x;

    const uint16_t* Kg = g_kb + (size_t)bh * NN * HD;
    const uint16_t* Vg = g_vtb + (size_t)bh * HD * NN;

    // loader: 4 threads/row, 32B each
    const int lrow = tid >> 2;
    const int lcq  = (tid & 3) * 16;
    const uint16_t* kpb = Kg + lrow * HD + lcq;
    const uint16_t* vpb = Vg + (size_t)lrow * NN + lcq;
    uint32_t skb[3], svb[3];
    #pragma unroll
    for (int s = 0; s < 3; s++) {
        skb[s] = smem_u32(Ksb + s * AT_STAGE + lrow * 72 + lcq);
        svb[s] = smem_u32(Vtb + s * AT_STAGE + lrow * 72 + lcq);
    }

    // ldmatrix lane offset (bytes): rows stride 144
    const uint32_t lmoff = ((lane >> 4) & 1) * 1152 + (lane & 7) * 144 +
                           ((lane >> 3) & 1) * 16;
    const uint32_t kfb0 = smem_u32(Ksb) + lmoff;
    const uint32_t vfb0 = smem_u32(Vtb) + lmoff;

    // prologue: tiles 0,1
    #pragma unroll
    for (int s = 0; s < 2; s++) {
        cp16(skb[s], kpb + (size_t)s * 64 * HD);
        cp16(skb[s] + 16, kpb + (size_t)s * 64 * HD + 8);
        cp16(svb[s], vpb + s * 64);
        cp16(svb[s] + 16, vpb + s * 64 + 8);
        cp_commit();
    }

    // Q fragments (bf16), resident
    const uint32_t* Qg32 =
        (const uint32_t*)(g_qb + ((size_t)bh * NN + qt * 128 + w * 16) * HD);
    uint32_t qf[4][4];
    #pragma unroll
    for (int kc = 0; kc < 4; kc++) {
        qf[kc][0] = Qg32[g * 32 + kc * 8 + cc];
        qf[kc][1] = Qg32[(g + 8) * 32 + kc * 8 + cc];
        qf[kc][2] = Qg32[g * 32 + kc * 8 + cc + 4];
        qf[kc][3] = Qg32[(g + 8) * 32 + kc * 8 + cc + 4];
    }

    float o[8][4];
    #pragma unroll
    for (int nt = 0; nt < 8; nt++)
        #pragma unroll
        for (int e = 0; e < 4; e++) o[nt][e] = 0.f;
    float m0 = -1e30f, m1 = -1e30f, l0 = 0.f, l1 = 0.f;

    for (int t = 0; t < 16; t++) {
        const int buf = t % 3;
        if (t < 15) cp_wait<1>(); else cp_wait<0>();
        __syncthreads();
        if (t + 2 < 16) {
            const int s = (t + 2) % 3;
            const uint16_t* kp = kpb + (size_t)(t + 2) * 64 * HD;
            const uint16_t* vp = vpb + (t + 2) * 64;
            cp16(skb[s], kp);  cp16(skb[s] + 16, kp + 8);
            cp16(svb[s], vp);  cp16(svb[s] + 16, vp + 8);
            cp_commit();
        }
        const uint32_t kfA = kfb0 + buf * AT_SBYTES;
        const uint32_t vfA = vfb0 + buf * AT_SBYTES;

        // ---- S = Q K^T ----
        float s[8][4];
        #pragma unroll
        for (int nt = 0; nt < 8; nt++)
            s[nt][0] = s[nt][1] = s[nt][2] = s[nt][3] = 0.f;
        #pragma unroll
        for (int np = 0; np < 4; np++) {
            #pragma unroll
            for (int kc = 0; kc < 4; kc++) {
                uint32_t t0, t1, t2, t3;
                ldsm4(t0, t1, t2, t3, kfA + np * 2304 + kc * 32);
                mma_bf16(s[2*np],     qf[kc], t0, t1);
                mma_bf16(s[2*np + 1], qf[kc], t2, t3);
            }
        }

        // ---- online softmax ----
        float rmax0 = -1e30f, rmax1 = -1e30f;
        #pragma unroll
        for (int nt = 0; nt < 8; nt++) {
            rmax0 = fmaxf(rmax0, fmaxf(s[nt][0], s[nt][1]));
            rmax1 = fmaxf(rmax1, fmaxf(s[nt][2], s[nt][3]));
        }
        rmax0 = fmaxf(rmax0, __shfl_xor_sync(0xffffffffu, rmax0, 1));
        rmax0 = fmaxf(rmax0, __shfl_xor_sync(0xffffffffu, rmax0, 2));
        rmax1 = fmaxf(rmax1, __shfl_xor_sync(0xffffffffu, rmax1, 1));
        rmax1 = fmaxf(rmax1, __shfl_xor_sync(0xffffffffu, rmax1, 2));
        float mn0 = fmaxf(m0, rmax0), mn1 = fmaxf(m1, rmax1);
        float sc0 = __expf(m0 - mn0), sc1 = __expf(m1 - mn1);
        m0 = mn0; m1 = mn1;
        float rs0 = 0.f, rs1 = 0.f;
        #pragma unroll
        for (int nt = 0; nt < 8; nt++) {
            s[nt][0] = __expf(s[nt][0] - mn0); rs0 += s[nt][0];
            s[nt][1] = __expf(s[nt][1] - mn0); rs0 += s[nt][1];
            s[nt][2] = __expf(s[nt][2] - mn1); rs1 += s[nt][2];
            s[nt][3] = __expf(s[nt][3] - mn1); rs1 += s[nt][3];
        }
        rs0 += __shfl_xor_sync(0xffffffffu, rs0, 1);
        rs0 += __shfl_xor_sync(0xffffffffu, rs0, 2);
        rs1 += __shfl_xor_sync(0xffffffffu, rs1, 1);
        rs1 += __shfl_xor_sync(0xffffffffu, rs1, 2);
        l0 = l0 * sc0 + rs0;
        l1 = l1 * sc1 + rs1;
        #pragma unroll
        for (int nt = 0; nt < 8; nt++) {
            o[nt][0] *= sc0; o[nt][1] *= sc0;
            o[nt][2] *= sc1; o[nt][3] *= sc1;
        }

        // ---- P: C-frag -> bf16 A-frag (register-only) ----
        uint32_t pa[4][4];
        #pragma unroll
        for (int kc = 0; kc < 4; kc++) {
            pa[kc][0] = pbf2(s[2 * kc][0],     s[2 * kc][1]);
            pa[kc][1] = pbf2(s[2 * kc][2],     s[2 * kc][3]);
            pa[kc][2] = pbf2(s[2 * kc + 1][0], s[2 * kc + 1][1]);
            pa[kc][3] = pbf2(s[2 * kc + 1][2], s[2 * kc + 1][3]);
        }

        // ---- O += P V ----
        #pragma unroll
        for (int np = 0; np < 4; np++) {
            #pragma unroll
            for (int kc = 0; kc < 4; kc++) {
                uint32_t t0, t1, t2, t3;
                ldsm4(t0, t1, t2, t3, vfA + np * 2304 + kc * 32);
                mma_bf16(o[2*np],     pa[kc], t0, t1);
                mma_bf16(o[2*np + 1], pa[kc], t2, t3);
            }
        }
    }

    // ---- output: bf16(o / (l * 32)) -> g_aob ----
    const int b = bh >> 4, head = bh & 15;
    const int row0 = qt * 128 + w * 16 + g;
    float inv0 = 1.0f / (l0 * 32.0f);
    float inv1 = 1.0f / (l1 * 32.0f);
    uint32_t* d0 = (uint32_t*)(g_aob + ((size_t)b * NN + row0) * DD + head * HD);
    uint32_t* d1 = (uint32_t*)(g_aob + ((size_t)b * NN + row0 + 8) * DD + head * HD);
    #pragma unroll
    for (int nt = 0; nt < 8; nt++) {
        d0[nt * 4 + cc] = pbf2(o[nt][0] * inv0, o[nt][1] * inv0);
        d1[nt * 4 + cc] = pbf2(o[nt][2] * inv1, o[nt][3] * inv1);
    }
}

// ================= gamma/beta GEMV (float4) =================
__global__ void __launch_bounds__(256) gammabeta_kernel(
    const float* __restrict__ w,  const float* __restrict__ Wg,
    const float* __restrict__ bg, const float* __restrict__ Wb,
    const float* __restrict__ bb)
{
    int lane = threadIdx.x & 31;
    int warp = threadIdx.x >> 5;
    int gid  = blockIdx.x * 8 + warp;
    int b = gid >> 10, d = gid & 1023;
    const float* wrow = w  + b * DD;
    const float* wg   = Wg + (size_t)d * DD;
    const float* wb   = Wb + (size_t)d * DD;
    float sg = 0.f, sb = 0.f;
    #pragma unroll
    for (int it = 0; it < 8; it++) {
        int k = it * 128 + lane * 4;
        float4 wk = *(const float4*)(wrow + k);
        float4 a  = *(const float4*)(wg + k);
        float4 c  = *(const float4*)(wb + k);
        sg = fmaf(wk.x, a.x, fmaf(wk.y, a.y, fmaf(wk.z, a.z, fmaf(wk.w, a.w, sg))));
        sb = fmaf(wk.x, c.x, fmaf(wk.y, c.y, fmaf(wk.z, c.z, fmaf(wk.w, c.w, sb))));
    }
    #pragma unroll
    for (int o = 16; o; o >>= 1) {
        sg += __shfl_xor_sync(0xffffffffu, sg, o);
        sb += __shfl_xor_sync(0xffffffffu, sb, o);
    }
    if (!lane) {
        g_gamma[gid] = sg + bg[d];
        g_beta[gid]  = sb + bb[d];
    }
}

// ================= SLN kernels =================
__device__ __forceinline__ void row_stats(float4 xv, float& mu, float& rstd,
                                          float* red)
{
    float s = xv.x + xv.y + xv.z + xv.w;
    float q = xv.x*xv.x + xv.y*xv.y + xv.z*xv.z + xv.w*xv.w;
    #pragma unroll
    for (int o = 16; o; o >>= 1) {
        s += __shfl_xor_sync(0xffffffffu, s, o);
        q += __shfl_xor_sync(0xffffffffu, q, o);
    }
    int warp = threadIdx.x >> 5, lane = threadIdx.x & 31;
    if (!lane) { red[warp] = s; red[8 + warp] = q; }
    __syncthreads();
    float ss = 0.f, qq = 0.f;
    #pragma unroll
    for (int i = 0; i < 8; i++) { ss += red[i]; qq += red[8 + i]; }
    mu = ss * (1.0f / DD);
    float var = qq * (1.0f / DD) - mu * mu;
    rstd = rsqrtf(var + 1e-5f);
}

__global__ void __launch_bounds__(256) sln1_kernel(
    const float* __restrict__ x, const float* __restrict__ ln_g,
    const float* __restrict__ ln_b)
{
    __shared__ float red[16];
    int row = blockIdx.x;
    int b = row >> 10;
    float4 xv = *(const float4*)(x + (size_t)row * DD + threadIdx.x * 4);
    float mu, rstd;
    row_stats(xv, mu, rstd, red);
    int d = threadIdx.x * 4;
    float4 g  = *(const float4*)(ln_g + d);
    float4 lb = *(const float4*)(ln_b + d);
    float4 ga = *(const float4*)(g_gamma + b * DD + d);
    float4 be = *(const float4*)(g_beta  + b * DD + d);
    float yx = fmaf(ga.x, fmaf((xv.x - mu) * rstd, g.x, lb.x), be.x);
    float yy = fmaf(ga.y, fmaf((xv.y - mu) * rstd, g.y, lb.y), be.y);
    float yz = fmaf(ga.z, fmaf((xv.z - mu) * rstd, g.z, lb.z), be.z);
    float yw = fmaf(ga.w, fmaf((xv.w - mu) * rstd, g.w, lb.w), be.w);
    *(uint2*)(g_hb + (size_t)row * DD + d) =
        make_uint2(pbf2(yx, yy), pbf2(yz, yw));
}

__global__ void __launch_bounds__(256) sln2_kernel(
    const float* __restrict__ ln_g, const float* __restrict__ ln_b,
    float* __restrict__ out)
{
    __shared__ float red[16];
    int row = blockIdx.x;
    int b = row >> 10;
    float4 xv = *(const float4*)(g_h1 + (size_t)row * DD + threadIdx.x * 4);
    float mu, rstd;
    row_stats(xv, mu, rstd, red);
    int d = threadIdx.x * 4;
    float4 g  = *(const float4*)(ln_g + d);
    float4 lb = *(const float4*)(ln_b + d);
    float4 ga = *(const float4*)(g_gamma + b * DD + d);
    float4 be = *(const float4*)(g_beta  + b * DD + d);
    float4 y;
    y.x = fmaf(ga.x, fmaf((xv.x - mu) * rstd, g.x, lb.x), be.x) + xv.x;
    y.y = fmaf(ga.y, fmaf((xv.y - mu) * rstd, g.y, lb.y), be.y) + xv.y;
    y.z = fmaf(ga.z, fmaf((xv.z - mu) * rstd, g.z, lb.z), be.z) + xv.z;
    y.w = fmaf(ga.w, fmaf((xv.w - mu) * rstd, g.w, lb.w), be.w) + xv.w;
    *(float4*)&out[(size_t)row * DD + d] = y;
}

// =====================================================================
extern "C" void kernel_launch(void* const* d_in, const int* in_sizes, int n_in,
                              void* d_out, int out_size)
{
    (void)in_sizes; (void)n_in; (void)out_size;
    const float* hidden = (const float*)d_in[0];
    const float* w      = (const float*)d_in[1];
    const float* ln_g   = (const float*)d_in[2];
    const float* ln_b   = (const float*)d_in[3];
    const float* Wg     = (const float*)d_in[4];
    const float* bg     = (const float*)d_in[5];
    const float* Wb     = (const float*)d_in[6];
    const float* bb     = (const float*)d_in[7];
    const float* Wqkv   = (const float*)d_in[8];
    const float* bqkv   = (const float*)d_in[9];
    const float* Wp     = (const float*)d_in[10];
    const float* bp     = (const float*)d_in[11];
    float* out = (float*)d_out;

    cudaFuncSetAttribute(mm_bf<1>, cudaFuncAttributeMaxDynamicSharedMemorySize, MM_DSMEM);
    cudaFuncSetAttribute(mm_bf<0>, cudaFuncAttributeMaxDynamicSharedMemorySize, MM_DSMEM);
    cudaFuncSetAttribute(attn_bf, cudaFuncAttributeMaxDynamicSharedMemorySize, AT_DSMEM);

    convert_w<<<(QKVN + DD) * DD / 1024, 256>>>(Wqkv, Wp);
    gammabeta_kernel<<<512, 256>>>(w, Wg, bg, Wb, bb);
    sln1_kernel<<<ROWS, 256>>>(hidden, ln_g, ln_b);
    mm_bf<1><<<dim3(QKVN / 128, ROWS / 128), 256, MM_DSMEM>>>(bqkv, hidden);
    attn_bf<<<dim3(NN / 128, BB * HH), 256, AT_DSMEM>>>();
    mm_bf<0><<<dim3(DD / 128, ROWS / 128), 256, MM_DSMEM>>>(bp, hidden);
    sln2_kernel<<<ROWS, 256>>>(ln_g, ln_b, out);
}